// round 1
// baseline (speedup 1.0000x reference)
#include <cuda_runtime.h>
#include <cuda_bf16.h>
#include <math.h>

// ---------------- problem constants ----------------
#define BSZ     2
#define SEQLEN  2048
#define DIM     2048
#define NH      16
#define NKV     4
#define HD      128
#define QKV_OUT 3072          // (16 + 2*4) * 128
#define TOKENS  (BSZ*SEQLEN)  // 4096
#define REPARAM_EPS 1e-6f
#define L2_EPS      1e-12f

// ---------------- device scratch (no allocations allowed) ----------------
__device__ float g_qkv_wn[QKV_OUT * DIM];   // 3072x2048
__device__ float g_out_wn[DIM * DIM];       // 2048x2048
__device__ float g_qkv   [TOKENS * QKV_OUT];// 4096x3072
__device__ float g_q     [TOKENS * NH  * HD];
__device__ float g_k     [TOKENS * NKV * HD];
__device__ float g_attn  [TOKENS * DIM];

// ---------------- weight row-normalization ----------------
__global__ void rownorm_kernel(const float* __restrict__ w,
                               float* __restrict__ wn, int K) {
    int r = blockIdx.x;
    const float* row = w + (size_t)r * K;
    float* orow = wn + (size_t)r * K;
    float ss = 0.f;
    for (int c = threadIdx.x * 4; c < K; c += blockDim.x * 4) {
        float4 v = *(const float4*)(row + c);
        ss += v.x*v.x + v.y*v.y + v.z*v.z + v.w*v.w;
    }
    // block reduce (256 threads = 8 warps)
    #pragma unroll
    for (int off = 16; off; off >>= 1) ss += __shfl_xor_sync(0xffffffffu, ss, off);
    __shared__ float sp[8];
    if ((threadIdx.x & 31) == 0) sp[threadIdx.x >> 5] = ss;
    __syncthreads();
    __shared__ float s_inv;
    if (threadIdx.x == 0) {
        float tot = 0.f;
        #pragma unroll
        for (int i = 0; i < 8; i++) tot += sp[i];
        s_inv = 1.f / (sqrtf(tot) + REPARAM_EPS);
    }
    __syncthreads();
    float inv = s_inv;
    for (int c = threadIdx.x * 4; c < K; c += blockDim.x * 4) {
        float4 v = *(const float4*)(row + c);
        v.x *= inv; v.y *= inv; v.z *= inv; v.w *= inv;
        *(float4*)(orow + c) = v;
    }
}

// ---------------- SGEMM: C[M,N] = A[M,K] @ B[N,K]^T ----------------
// 128x128 tile, BK=8, 256 threads, 8x8 per thread.
__global__ __launch_bounds__(256) void sgemm_nt(const float* __restrict__ A,
                                                const float* __restrict__ B,
                                                float* __restrict__ C,
                                                int M, int N, int K) {
    __shared__ float As[8][128];
    __shared__ float Bs[8][128];
    int tid = threadIdx.x;
    int bm = blockIdx.y * 128, bn = blockIdx.x * 128;
    int lr = tid >> 1;           // 0..127
    int lc = (tid & 1) * 4;      // 0 or 4
    const float* Aptr = A + (size_t)(bm + lr) * K + lc;
    const float* Bptr = B + (size_t)(bn + lr) * K + lc;

    float acc[8][8];
    #pragma unroll
    for (int i = 0; i < 8; i++)
        #pragma unroll
        for (int j = 0; j < 8; j++) acc[i][j] = 0.f;

    int tx = tid & 15, ty = tid >> 4;

    for (int k0 = 0; k0 < K; k0 += 8) {
        float4 av = *(const float4*)(Aptr + k0);
        float4 bv = *(const float4*)(Bptr + k0);
        As[lc + 0][lr] = av.x; As[lc + 1][lr] = av.y;
        As[lc + 2][lr] = av.z; As[lc + 3][lr] = av.w;
        Bs[lc + 0][lr] = bv.x; Bs[lc + 1][lr] = bv.y;
        Bs[lc + 2][lr] = bv.z; Bs[lc + 3][lr] = bv.w;
        __syncthreads();
        #pragma unroll
        for (int kk = 0; kk < 8; kk++) {
            float a[8], b[8];
            #pragma unroll
            for (int i = 0; i < 4; i++) {
                ((float4*)a)[0] = *(float4*)&As[kk][ty * 8];
                ((float4*)a)[1] = *(float4*)&As[kk][ty * 8 + 4];
                ((float4*)b)[0] = *(float4*)&Bs[kk][tx * 8];
                ((float4*)b)[1] = *(float4*)&Bs[kk][tx * 8 + 4];
                break;
            }
            #pragma unroll
            for (int i = 0; i < 8; i++)
                #pragma unroll
                for (int j = 0; j < 8; j++) acc[i][j] += a[i] * b[j];
        }
        __syncthreads();
    }
    #pragma unroll
    for (int i = 0; i < 8; i++) {
        float* crow = C + (size_t)(bm + ty * 8 + i) * N + bn + tx * 8;
        *(float4*)(crow)     = make_float4(acc[i][0], acc[i][1], acc[i][2], acc[i][3]);
        *(float4*)(crow + 4) = make_float4(acc[i][4], acc[i][5], acc[i][6], acc[i][7]);
    }
}

// ---------------- RoPE + l2-normalize + scale ----------------
// grid: (TOKENS, 20) heads 0..15 = Q, 16..19 = K. 64 threads (one per pair).
__global__ void rope_norm_kernel(const float* __restrict__ qkv,
                                 const float* __restrict__ fc,
                                 const float* __restrict__ fs,
                                 const float* __restrict__ s_q,
                                 const float* __restrict__ s_k,
                                 float* __restrict__ qout,
                                 float* __restrict__ kout) {
    int t = blockIdx.x;
    int h = blockIdx.y;
    int i = threadIdx.x;                 // pair index 0..63
    int s = t & (SEQLEN - 1);
    const float* base = qkv + (size_t)t * QKV_OUT + h * HD; // works for q and k heads
    float xr = base[2 * i], xi = base[2 * i + 1];
    float c = fc[s * 64 + i], sn = fs[s * 64 + i];
    float orr = xr * c - xi * sn;
    float oi  = xr * sn + xi * c;
    float ss = orr * orr + oi * oi;
    #pragma unroll
    for (int off = 16; off; off >>= 1) ss += __shfl_xor_sync(0xffffffffu, ss, off);
    __shared__ float part[2];
    if ((i & 31) == 0) part[i >> 5] = ss;
    __syncthreads();
    float tot = part[0] + part[1];
    float inv = 1.f / (sqrtf(tot) + L2_EPS);
    const float* sc = (h < NH) ? s_q : s_k;
    float* out = (h < NH) ? (qout + (size_t)t * (NH * HD) + h * HD)
                          : (kout + (size_t)t * (NKV * HD) + (h - NH) * HD);
    out[2 * i]     = orr * inv * sc[2 * i];
    out[2 * i + 1] = oi  * inv * sc[2 * i + 1];
}

// ---------------- flash attention ----------------
// grid (32 qblocks, 16 heads, 2 batch), 256 threads. BQ=BK=64.
#define QS_STRIDE 132
#define PS_STRIDE 68
#define FLASH_SMEM ((3 * 64 * QS_STRIDE + 64 * PS_STRIDE + 64) * 4)

__global__ __launch_bounds__(256) void flash_kernel(const float* __restrict__ Q,
                                                    const float* __restrict__ Kt,
                                                    const float* __restrict__ QKV,
                                                    const int* __restrict__ mask,
                                                    float* __restrict__ O) {
    extern __shared__ float sm[];
    float* Qs = sm;                               // 64 x 132
    float* Ks = Qs + 64 * QS_STRIDE;              // 64 x 132
    float* Vs = Ks + 64 * QS_STRIDE;              // 64 x 132
    float* Ps = Vs + 64 * QS_STRIDE;              // 64 x 68
    float* Bias = Ps + 64 * PS_STRIDE;            // 64

    int qb = blockIdx.x, h = blockIdx.y, b = blockIdx.z;
    int tid = threadIdx.x;
    int hk = h >> 2;                              // GQA: kv head = h / 4
    int q0 = qb * 64;

    // load Q tile (64 x 128 floats = 2048 float4)
    for (int idx = tid; idx < 2048; idx += 256) {
        int r = idx >> 5, c4 = (idx & 31) << 2;
        *(float4*)&Qs[r * QS_STRIDE + c4] =
            *(const float4*)&Q[((size_t)(b * SEQLEN + q0 + r)) * (NH * HD) + h * HD + c4];
    }

    int row = tid >> 2;     // 0..63
    int grp = tid & 3;      // 0..3
    float o[32];
    #pragma unroll
    for (int i = 0; i < 32; i++) o[i] = 0.f;
    float m = -1e30f, l = 0.f;
    const float scale = 11.313708498984761f; // sqrt(128)

    for (int kb = 0; kb < SEQLEN / 64; kb++) {
        int k0 = kb * 64;
        __syncthreads();  // protect Ps/Vs reads from previous iteration
        for (int idx = tid; idx < 2048; idx += 256) {
            int r = idx >> 5, c4 = (idx & 31) << 2;
            *(float4*)&Ks[r * QS_STRIDE + c4] =
                *(const float4*)&Kt[((size_t)(b * SEQLEN + k0 + r)) * (NKV * HD) + hk * HD + c4];
            *(float4*)&Vs[r * QS_STRIDE + c4] =
                *(const float4*)&QKV[((size_t)(b * SEQLEN + k0 + r)) * QKV_OUT + 2560 + hk * HD + c4];
        }
        if (tid < 64) Bias[tid] = mask[b * SEQLEN + k0 + tid] ? 0.f : -1e30f;
        __syncthreads();

        // scores: this thread -> row, keys grp*16 .. grp*16+15
        float s[16];
        #pragma unroll
        for (int j = 0; j < 16; j++) s[j] = 0.f;
        #pragma unroll 4
        for (int d = 0; d < 128; d += 4) {
            float4 qv = *(float4*)&Qs[row * QS_STRIDE + d];
            #pragma unroll
            for (int j = 0; j < 16; j++) {
                float4 kv = *(float4*)&Ks[(grp * 16 + j) * QS_STRIDE + d];
                s[j] += qv.x * kv.x + qv.y * kv.y + qv.z * kv.z + qv.w * kv.w;
            }
        }
        #pragma unroll
        for (int j = 0; j < 16; j++) s[j] = s[j] * scale + Bias[grp * 16 + j];

        // online softmax (reduce over 4-lane group: xor 1, 2)
        float mx = s[0];
        #pragma unroll
        for (int j = 1; j < 16; j++) mx = fmaxf(mx, s[j]);
        mx = fmaxf(mx, __shfl_xor_sync(0xffffffffu, mx, 1));
        mx = fmaxf(mx, __shfl_xor_sync(0xffffffffu, mx, 2));
        float m_new = fmaxf(m, mx);
        float corr = __expf(m - m_new);
        float lsum = 0.f;
        #pragma unroll
        for (int j = 0; j < 16; j++) { s[j] = __expf(s[j] - m_new); lsum += s[j]; }
        lsum += __shfl_xor_sync(0xffffffffu, lsum, 1);
        lsum += __shfl_xor_sync(0xffffffffu, lsum, 2);
        l = l * corr + lsum;
        m = m_new;
        #pragma unroll
        for (int i = 0; i < 32; i++) o[i] *= corr;

        #pragma unroll
        for (int j = 0; j < 16; j++) Ps[row * PS_STRIDE + grp * 16 + j] = s[j];
        __syncthreads();

        // accumulate: o[grp*32 .. grp*32+31] over all 64 keys
        #pragma unroll 4
        for (int kk = 0; kk < 64; kk++) {
            float p = Ps[row * PS_STRIDE + kk];
            const float* vrow = &Vs[kk * QS_STRIDE + grp * 32];
            #pragma unroll
            for (int i = 0; i < 32; i += 4) {
                float4 vv = *(const float4*)&vrow[i];
                o[i]     += p * vv.x;
                o[i + 1] += p * vv.y;
                o[i + 2] += p * vv.z;
                o[i + 3] += p * vv.w;
            }
        }
    }

    float inv = 1.f / l;
    float* orow = O + ((size_t)(b * SEQLEN + q0 + row)) * DIM + h * HD + grp * 32;
    #pragma unroll
    for (int i = 0; i < 32; i += 4) {
        *(float4*)&orow[i] = make_float4(o[i] * inv, o[i + 1] * inv,
                                         o[i + 2] * inv, o[i + 3] * inv);
    }
}

// ---------------- launch ----------------
extern "C" void kernel_launch(void* const* d_in, const int* in_sizes, int n_in,
                              void* d_out, int out_size) {
    const float* x     = (const float*)d_in[0];
    const int*   mask  = (const int*)  d_in[1];
    const float* fc    = (const float*)d_in[2];
    const float* fs    = (const float*)d_in[3];
    const float* qkv_w = (const float*)d_in[4];
    const float* out_w = (const float*)d_in[5];
    const float* s_q   = (const float*)d_in[6];
    const float* s_k   = (const float*)d_in[7];
    float* out = (float*)d_out;

    void *p0, *p1, *p2, *p3, *p4, *p5;
    cudaGetSymbolAddress(&p0, g_qkv_wn);
    cudaGetSymbolAddress(&p1, g_out_wn);
    cudaGetSymbolAddress(&p2, g_qkv);
    cudaGetSymbolAddress(&p3, g_q);
    cudaGetSymbolAddress(&p4, g_k);
    cudaGetSymbolAddress(&p5, g_attn);
    float* qkv_wn = (float*)p0;
    float* out_wn = (float*)p1;
    float* qkv    = (float*)p2;
    float* q      = (float*)p3;
    float* k      = (float*)p4;
    float* attn   = (float*)p5;

    cudaFuncSetAttribute(flash_kernel,
                         cudaFuncAttributeMaxDynamicSharedMemorySize, FLASH_SMEM);

    // 1. normalize weights
    rownorm_kernel<<<QKV_OUT, 256>>>(qkv_w, qkv_wn, DIM);
    rownorm_kernel<<<DIM, 256>>>(out_w, out_wn, DIM);

    // 2. QKV projection: [4096,3072] = [4096,2048] @ [3072,2048]^T
    sgemm_nt<<<dim3(QKV_OUT / 128, TOKENS / 128), 256>>>(x, qkv_wn, qkv,
                                                         TOKENS, QKV_OUT, DIM);

    // 3. RoPE + l2norm + scale
    rope_norm_kernel<<<dim3(TOKENS, NH + NKV), 64>>>(qkv, fc, fs, s_q, s_k, q, k);

    // 4. flash attention
    flash_kernel<<<dim3(SEQLEN / 64, NH, BSZ), 256, FLASH_SMEM>>>(q, k, qkv, mask, attn);

    // 5. output projection: [4096,2048] = [4096,2048] @ [2048,2048]^T
    sgemm_nt<<<dim3(DIM / 128, TOKENS / 128), 256>>>(attn, out_wn, out,
                                                     TOKENS, DIM, DIM);
}

// round 2
// speedup vs baseline: 9.8136x; 9.8136x over previous
#include <cuda_runtime.h>
#include <cuda_bf16.h>
#include <math.h>

// ---------------- problem constants ----------------
#define BSZ     2
#define SEQLEN  2048
#define DIM     2048
#define NH      16
#define NKV     4
#define HD      128
#define QKV_OUT 3072
#define TOKENS  (BSZ*SEQLEN)
#define REPARAM_EPS 1e-6f
#define L2_EPS      1e-12f

// ---------------- device scratch ----------------
__device__ float g_qkv   [TOKENS * QKV_OUT];
__device__ float g_q     [TOKENS * NH  * HD];
__device__ float g_k     [TOKENS * NKV * HD];
__device__ float g_attn  [TOKENS * DIM];
__device__ float g_qinv  [QKV_OUT];
__device__ float g_oinv  [DIM];

// ---------------- helpers ----------------
__device__ __forceinline__ unsigned f2tf(float x) {
    unsigned r;
    asm("cvt.rna.tf32.f32 %0, %1;" : "=r"(r) : "f"(x));
    return r;
}

__device__ __forceinline__ void mma8(float* c, const unsigned* a, unsigned b0, unsigned b1) {
    asm volatile(
        "mma.sync.aligned.m16n8k8.row.col.f32.tf32.tf32.f32 "
        "{%0,%1,%2,%3},{%4,%5,%6,%7},{%8,%9},{%0,%1,%2,%3};"
        : "+f"(c[0]), "+f"(c[1]), "+f"(c[2]), "+f"(c[3])
        : "r"(a[0]), "r"(a[1]), "r"(a[2]), "r"(a[3]), "r"(b0), "r"(b1));
}

// ---------------- weight row inverse-norm ----------------
__global__ void rownorm_inv_kernel(const float* __restrict__ w,
                                   float* __restrict__ inv, int K) {
    int r = blockIdx.x;
    const float* row = w + (size_t)r * K;
    float ss = 0.f;
    for (int c = threadIdx.x * 4; c < K; c += blockDim.x * 4) {
        float4 v = *(const float4*)(row + c);
        ss += v.x*v.x + v.y*v.y + v.z*v.z + v.w*v.w;
    }
    #pragma unroll
    for (int off = 16; off; off >>= 1) ss += __shfl_xor_sync(0xffffffffu, ss, off);
    __shared__ float sp[8];
    if ((threadIdx.x & 31) == 0) sp[threadIdx.x >> 5] = ss;
    __syncthreads();
    if (threadIdx.x == 0) {
        float tot = 0.f;
        #pragma unroll
        for (int i = 0; i < 8; i++) tot += sp[i];
        inv[r] = 1.f / (sqrtf(tot) + REPARAM_EPS);
    }
}

// ---------------- TF32 tensor-core GEMM: C[M,N] = A[M,K] @ (diag(binv) B[N,K])^T ----
// 128x128 tile, BK=16, 256 threads = 8 warps (4x2), each warp 32x64.
#define GSTR 20  // smem row stride (words) for 16 k-values + pad

__global__ __launch_bounds__(256) void gemm_tf32(const float* __restrict__ A,
                                                 const float* __restrict__ B,
                                                 const float* __restrict__ binv,
                                                 float* __restrict__ C,
                                                 int M, int N, int K) {
    __shared__ unsigned As[128][GSTR];
    __shared__ unsigned Bs[128][GSTR];
    int tid = threadIdx.x, lane = tid & 31, wid = tid >> 5;
    int wm = wid & 3, wn = wid >> 2;
    int g = lane >> 2, t = lane & 3;
    int bm = blockIdx.y * 128, bn = blockIdx.x * 128;
    int lr = tid >> 2, lk = (tid & 3) << 2;

    float inv0 = binv[bn + lr], inv1 = binv[bn + lr + 64];

    float acc[2][8][4];
    #pragma unroll
    for (int mt = 0; mt < 2; mt++)
        #pragma unroll
        for (int nt = 0; nt < 8; nt++)
            #pragma unroll
            for (int i = 0; i < 4; i++) acc[mt][nt][i] = 0.f;

    const float* Ap0 = A + (size_t)(bm + lr) * K + lk;
    const float* Ap1 = Ap0 + (size_t)64 * K;
    const float* Bp0 = B + (size_t)(bn + lr) * K + lk;
    const float* Bp1 = Bp0 + (size_t)64 * K;

    for (int k0 = 0; k0 < K; k0 += 16) {
        float4 av0 = *(const float4*)(Ap0 + k0);
        float4 av1 = *(const float4*)(Ap1 + k0);
        float4 bv0 = *(const float4*)(Bp0 + k0);
        float4 bv1 = *(const float4*)(Bp1 + k0);
        __syncthreads();
        *(uint4*)&As[lr][lk]      = make_uint4(f2tf(av0.x), f2tf(av0.y), f2tf(av0.z), f2tf(av0.w));
        *(uint4*)&As[lr + 64][lk] = make_uint4(f2tf(av1.x), f2tf(av1.y), f2tf(av1.z), f2tf(av1.w));
        *(uint4*)&Bs[lr][lk]      = make_uint4(f2tf(bv0.x*inv0), f2tf(bv0.y*inv0), f2tf(bv0.z*inv0), f2tf(bv0.w*inv0));
        *(uint4*)&Bs[lr + 64][lk] = make_uint4(f2tf(bv1.x*inv1), f2tf(bv1.y*inv1), f2tf(bv1.z*inv1), f2tf(bv1.w*inv1));
        __syncthreads();
        #pragma unroll
        for (int kk = 0; kk < 16; kk += 8) {
            unsigned af[2][4];
            #pragma unroll
            for (int mt = 0; mt < 2; mt++) {
                int m = wm * 32 + mt * 16 + g;
                af[mt][0] = As[m][kk + t];
                af[mt][1] = As[m + 8][kk + t];
                af[mt][2] = As[m][kk + t + 4];
                af[mt][3] = As[m + 8][kk + t + 4];
            }
            #pragma unroll
            for (int nt = 0; nt < 8; nt++) {
                int n = wn * 64 + nt * 8 + g;
                unsigned b0 = Bs[n][kk + t], b1 = Bs[n][kk + t + 4];
                mma8(acc[0][nt], af[0], b0, b1);
                mma8(acc[1][nt], af[1], b0, b1);
            }
        }
    }
    #pragma unroll
    for (int mt = 0; mt < 2; mt++) {
        int r0 = bm + wm * 32 + mt * 16 + g;
        #pragma unroll
        for (int nt = 0; nt < 8; nt++) {
            int c = bn + wn * 64 + nt * 8 + 2 * t;
            *(float2*)&C[(size_t)r0 * N + c]       = make_float2(acc[mt][nt][0], acc[mt][nt][1]);
            *(float2*)&C[(size_t)(r0 + 8) * N + c] = make_float2(acc[mt][nt][2], acc[mt][nt][3]);
        }
    }
}

// ---------------- RoPE + l2-normalize + scale ----------------
__global__ void rope_norm_kernel(const float* __restrict__ qkv,
                                 const float* __restrict__ fc,
                                 const float* __restrict__ fs,
                                 const float* __restrict__ s_q,
                                 const float* __restrict__ s_k,
                                 float* __restrict__ qout,
                                 float* __restrict__ kout) {
    int t = blockIdx.x;
    int h = blockIdx.y;
    int i = threadIdx.x;
    int s = t & (SEQLEN - 1);
    const float* base = qkv + (size_t)t * QKV_OUT + h * HD;
    float xr = base[2 * i], xi = base[2 * i + 1];
    float c = fc[s * 64 + i], sn = fs[s * 64 + i];
    float orr = xr * c - xi * sn;
    float oi  = xr * sn + xi * c;
    float ss = orr * orr + oi * oi;
    #pragma unroll
    for (int off = 16; off; off >>= 1) ss += __shfl_xor_sync(0xffffffffu, ss, off);
    __shared__ float part[2];
    if ((i & 31) == 0) part[i >> 5] = ss;
    __syncthreads();
    float tot = part[0] + part[1];
    float inv = 1.f / (sqrtf(tot) + L2_EPS);
    const float* sc = (h < NH) ? s_q : s_k;
    float* out = (h < NH) ? (qout + (size_t)t * (NH * HD) + h * HD)
                          : (kout + (size_t)t * (NKV * HD) + (h - NH) * HD);
    out[2 * i]     = orr * inv * sc[2 * i];
    out[2 * i + 1] = oi  * inv * sc[2 * i + 1];
}

// ---------------- TF32 flash attention ----------------
// grid (32 qblocks, 16 heads, 2 batch), 256 threads = 8 warps (4x2).
// BQ=64, BK=32. Warp computes: scores 16x16, output 16x64.
#define QSTR 132
#define VSTR 136
#define PSTR 36
#define FSMEM ((64*QSTR + 32*QSTR + 32*VSTR + 64*PSTR + 288) * 4)

__global__ __launch_bounds__(256) void flash_tf32(const float* __restrict__ Q,
                                                  const float* __restrict__ Kg,
                                                  const float* __restrict__ QKV,
                                                  const int* __restrict__ mask,
                                                  float* __restrict__ O) {
    extern __shared__ unsigned sm[];
    unsigned* Qs = sm;                    // 64 x 132, row-major [q][d]
    unsigned* Ks = Qs + 64 * QSTR;        // 32 x 132, row-major [key][d]
    unsigned* Vs = Ks + 32 * QSTR;        // 32 x 136, row-major [key][d]
    unsigned* Ps = Vs + 32 * VSTR;        // 64 x 36,  row-major [q][key]
    float* redm  = (float*)(Ps + 64 * PSTR);   // [2][64]
    float* reds  = redm + 128;                  // [2][64]
    float* sbias = reds + 128;                  // [32]

    int tid = threadIdx.x, lane = tid & 31, wid = tid >> 5;
    int wm = wid & 3, wn = wid >> 2;
    int g = lane >> 2, t = lane & 3;
    int qb = blockIdx.x, h = blockIdx.y, b = blockIdx.z;
    int hk = h >> 2;
    int q0 = qb * 64;
    int qrow = wm * 16 + g;
    const float scale = 11.313708498984761f; // sqrt(128)

    // load Q tile (64 x 128)
    for (int idx = tid; idx < 2048; idx += 256) {
        int r = idx >> 5, c4 = (idx & 31) << 2;
        float4 v = *(const float4*)&Q[(size_t)(b * SEQLEN + q0 + r) * (NH * HD) + h * HD + c4];
        unsigned* dst = &Qs[r * QSTR + c4];
        dst[0] = f2tf(v.x); dst[1] = f2tf(v.y); dst[2] = f2tf(v.z); dst[3] = f2tf(v.w);
    }

    float o[8][4];
    #pragma unroll
    for (int j = 0; j < 8; j++)
        #pragma unroll
        for (int i = 0; i < 4; i++) o[j][i] = 0.f;
    float mrow0 = -1e30f, mrow1 = -1e30f, lrow0 = 0.f, lrow1 = 0.f;

    for (int kb = 0; kb < SEQLEN / 32; kb++) {
        int k0 = kb * 32;
        __syncthreads();  // prev iteration's Ps/Vs/red reads complete
        for (int idx = tid; idx < 1024; idx += 256) {
            int r = idx >> 5, c4 = (idx & 31) << 2;
            float4 kv = *(const float4*)&Kg[(size_t)(b * SEQLEN + k0 + r) * (NKV * HD) + hk * HD + c4];
            unsigned* kd = &Ks[r * QSTR + c4];
            kd[0] = f2tf(kv.x); kd[1] = f2tf(kv.y); kd[2] = f2tf(kv.z); kd[3] = f2tf(kv.w);
            float4 vv = *(const float4*)&QKV[(size_t)(b * SEQLEN + k0 + r) * QKV_OUT + 2560 + hk * HD + c4];
            unsigned* vd = &Vs[r * VSTR + c4];
            vd[0] = f2tf(vv.x); vd[1] = f2tf(vv.y); vd[2] = f2tf(vv.z); vd[3] = f2tf(vv.w);
        }
        if (tid < 32) sbias[tid] = mask[b * SEQLEN + k0 + tid] ? 0.f : -1e30f;
        __syncthreads();

        // ---- QK^T: scores 16x16 per warp ----
        float sc[2][4];
        #pragma unroll
        for (int j = 0; j < 2; j++)
            #pragma unroll
            for (int i = 0; i < 4; i++) sc[j][i] = 0.f;
        #pragma unroll
        for (int kk = 0; kk < 128; kk += 8) {
            unsigned a[4];
            a[0] = Qs[qrow * QSTR + kk + t];
            a[1] = Qs[(qrow + 8) * QSTR + kk + t];
            a[2] = Qs[qrow * QSTR + kk + t + 4];
            a[3] = Qs[(qrow + 8) * QSTR + kk + t + 4];
            #pragma unroll
            for (int j = 0; j < 2; j++) {
                int n = wn * 16 + j * 8 + g;
                unsigned b0 = Ks[n * QSTR + kk + t], b1 = Ks[n * QSTR + kk + t + 4];
                mma8(sc[j], a, b0, b1);
            }
        }
        #pragma unroll
        for (int j = 0; j < 2; j++) {
            int c = wn * 16 + j * 8 + 2 * t;
            float b0 = sbias[c], b1 = sbias[c + 1];
            sc[j][0] = sc[j][0] * scale + b0;
            sc[j][1] = sc[j][1] * scale + b1;
            sc[j][2] = sc[j][2] * scale + b0;
            sc[j][3] = sc[j][3] * scale + b1;
        }

        // ---- online softmax ----
        float mx0 = fmaxf(fmaxf(sc[0][0], sc[0][1]), fmaxf(sc[1][0], sc[1][1]));
        float mx1 = fmaxf(fmaxf(sc[0][2], sc[0][3]), fmaxf(sc[1][2], sc[1][3]));
        mx0 = fmaxf(mx0, __shfl_xor_sync(0xffffffffu, mx0, 1));
        mx0 = fmaxf(mx0, __shfl_xor_sync(0xffffffffu, mx0, 2));
        mx1 = fmaxf(mx1, __shfl_xor_sync(0xffffffffu, mx1, 1));
        mx1 = fmaxf(mx1, __shfl_xor_sync(0xffffffffu, mx1, 2));
        if (t == 0) { redm[wn * 64 + qrow] = mx0; redm[wn * 64 + qrow + 8] = mx1; }
        __syncthreads();
        float mnew0 = fmaxf(mrow0, fmaxf(redm[qrow], redm[64 + qrow]));
        float mnew1 = fmaxf(mrow1, fmaxf(redm[qrow + 8], redm[64 + qrow + 8]));
        float corr0 = __expf(mrow0 - mnew0);
        float corr1 = __expf(mrow1 - mnew1);

        float p[2][4];
        float s0 = 0.f, s1 = 0.f;
        #pragma unroll
        for (int j = 0; j < 2; j++) {
            p[j][0] = __expf(sc[j][0] - mnew0);
            p[j][1] = __expf(sc[j][1] - mnew0);
            p[j][2] = __expf(sc[j][2] - mnew1);
            p[j][3] = __expf(sc[j][3] - mnew1);
            s0 += p[j][0] + p[j][1];
            s1 += p[j][2] + p[j][3];
        }
        s0 += __shfl_xor_sync(0xffffffffu, s0, 1);
        s0 += __shfl_xor_sync(0xffffffffu, s0, 2);
        s1 += __shfl_xor_sync(0xffffffffu, s1, 1);
        s1 += __shfl_xor_sync(0xffffffffu, s1, 2);
        if (t == 0) { reds[wn * 64 + qrow] = s0; reds[wn * 64 + qrow + 8] = s1; }
        #pragma unroll
        for (int j = 0; j < 2; j++) {
            int c = wn * 16 + j * 8 + 2 * t;
            *(uint2*)&Ps[qrow * PSTR + c]       = make_uint2(f2tf(p[j][0]), f2tf(p[j][1]));
            *(uint2*)&Ps[(qrow + 8) * PSTR + c] = make_uint2(f2tf(p[j][2]), f2tf(p[j][3]));
        }
        __syncthreads();
        float ls0 = reds[qrow] + reds[64 + qrow];
        float ls1 = reds[qrow + 8] + reds[64 + qrow + 8];
        lrow0 = lrow0 * corr0 + ls0;
        lrow1 = lrow1 * corr1 + ls1;
        mrow0 = mnew0; mrow1 = mnew1;
        #pragma unroll
        for (int j = 0; j < 8; j++) {
            o[j][0] *= corr0; o[j][1] *= corr0;
            o[j][2] *= corr1; o[j][3] *= corr1;
        }

        // ---- P @ V: 16x64 per warp ----
        #pragma unroll
        for (int kk = 0; kk < 32; kk += 8) {
            unsigned a[4];
            a[0] = Ps[qrow * PSTR + kk + t];
            a[1] = Ps[(qrow + 8) * PSTR + kk + t];
            a[2] = Ps[qrow * PSTR + kk + t + 4];
            a[3] = Ps[(qrow + 8) * PSTR + kk + t + 4];
            #pragma unroll
            for (int j = 0; j < 8; j++) {
                int n = wn * 64 + j * 8 + g;
                unsigned b0 = Vs[(kk + t) * VSTR + n], b1 = Vs[(kk + t + 4) * VSTR + n];
                mma8(o[j], a, b0, b1);
            }
        }
    }

    float i0 = 1.f / lrow0, i1 = 1.f / lrow1;
    #pragma unroll
    for (int j = 0; j < 8; j++) {
        int c = h * HD + wn * 64 + j * 8 + 2 * t;
        float* r0 = &O[(size_t)(b * SEQLEN + q0 + qrow) * DIM + c];
        float* r1 = &O[(size_t)(b * SEQLEN + q0 + qrow + 8) * DIM + c];
        *(float2*)r0 = make_float2(o[j][0] * i0, o[j][1] * i0);
        *(float2*)r1 = make_float2(o[j][2] * i1, o[j][3] * i1);
    }
}

// ---------------- launch ----------------
extern "C" void kernel_launch(void* const* d_in, const int* in_sizes, int n_in,
                              void* d_out, int out_size) {
    const float* x     = (const float*)d_in[0];
    const int*   mask  = (const int*)  d_in[1];
    const float* fc    = (const float*)d_in[2];
    const float* fs    = (const float*)d_in[3];
    const float* qkv_w = (const float*)d_in[4];
    const float* out_w = (const float*)d_in[5];
    const float* s_q   = (const float*)d_in[6];
    const float* s_k   = (const float*)d_in[7];
    float* out = (float*)d_out;

    void *p2, *p3, *p4, *p5, *p6, *p7;
    cudaGetSymbolAddress(&p2, g_qkv);
    cudaGetSymbolAddress(&p3, g_q);
    cudaGetSymbolAddress(&p4, g_k);
    cudaGetSymbolAddress(&p5, g_attn);
    cudaGetSymbolAddress(&p6, g_qinv);
    cudaGetSymbolAddress(&p7, g_oinv);
    float* qkv  = (float*)p2;
    float* q    = (float*)p3;
    float* k    = (float*)p4;
    float* attn = (float*)p5;
    float* qinv = (float*)p6;
    float* oinv = (float*)p7;

    cudaFuncSetAttribute(flash_tf32,
                         cudaFuncAttributeMaxDynamicSharedMemorySize, FSMEM);

    // 1. weight row inverse norms (fused into GEMMs as column scales)
    rownorm_inv_kernel<<<QKV_OUT, 256>>>(qkv_w, qinv, DIM);
    rownorm_inv_kernel<<<DIM, 256>>>(out_w, oinv, DIM);

    // 2. QKV projection
    gemm_tf32<<<dim3(QKV_OUT / 128, TOKENS / 128), 256>>>(x, qkv_w, qinv, qkv,
                                                          TOKENS, QKV_OUT, DIM);

    // 3. RoPE + l2norm + scale
    rope_norm_kernel<<<dim3(TOKENS, NH + NKV), 64>>>(qkv, fc, fs, s_q, s_k, q, k);

    // 4. flash attention (tensor cores)
    flash_tf32<<<dim3(SEQLEN / 64, NH, BSZ), 256, FSMEM>>>(q, k, qkv, mask, attn);

    // 5. output projection
    gemm_tf32<<<dim3(DIM / 128, TOKENS / 128), 256>>>(attn, out_w, oinv, out,
                                                      TOKENS, DIM, DIM);
}

// round 3
// speedup vs baseline: 26.7516x; 2.7260x over previous
#include <cuda_runtime.h>
#include <cuda_fp16.h>
#include <math.h>

// ---------------- problem constants ----------------
#define BSZ     2
#define SEQLEN  2048
#define DIM     2048
#define NH      16
#define NKV     4
#define HD      128
#define QKV_OUT 3072
#define TOKENS  (BSZ*SEQLEN)
#define REPARAM_EPS 1e-6f
#define L2_EPS      1e-12f

// ---------------- device scratch ----------------
__device__ float  g_qkv  [TOKENS * QKV_OUT];       // fp32 qkv (feeds rope in fp32)
__device__ __half g_xh   [TOKENS * DIM];
__device__ __half g_wqh  [QKV_OUT * DIM];          // row-normalized fp16 qkv weight
__device__ __half g_woh  [DIM * DIM];              // row-normalized fp16 out weight
__device__ __half g_qh   [TOKENS * NH  * HD];
__device__ __half g_kh   [TOKENS * NKV * HD];
__device__ __half g_vh   [TOKENS * NKV * HD];
__device__ __half g_attnh[TOKENS * DIM];

// ---------------- helpers ----------------
__device__ __forceinline__ void mma16(float* c, const unsigned* a, unsigned b0, unsigned b1) {
    asm volatile(
        "mma.sync.aligned.m16n8k16.row.col.f32.f16.f16.f32 "
        "{%0,%1,%2,%3},{%4,%5,%6,%7},{%8,%9},{%0,%1,%2,%3};"
        : "+f"(c[0]), "+f"(c[1]), "+f"(c[2]), "+f"(c[3])
        : "r"(a[0]), "r"(a[1]), "r"(a[2]), "r"(a[3]), "r"(b0), "r"(b1));
}
__device__ __forceinline__ unsigned smem_u32(const void* p) {
    return (unsigned)__cvta_generic_to_shared(p);
}
__device__ __forceinline__ void cp16(unsigned dst, const void* src) {
    asm volatile("cp.async.cg.shared.global [%0], [%1], 16;" :: "r"(dst), "l"(src));
}
#define CP_COMMIT() asm volatile("cp.async.commit_group;")
#define CP_WAIT(n)  asm volatile("cp.async.wait_group %0;" :: "n"(n))

// ---------------- fp32 -> fp16 bulk convert ----------------
__global__ void f2h_kernel(const float* __restrict__ x, __half* __restrict__ xh, int n) {
    int i = (blockIdx.x * blockDim.x + threadIdx.x) * 8;
    if (i < n) {
        float4 a = *(const float4*)(x + i);
        float4 b = *(const float4*)(x + i + 4);
        __half2 h0 = __floats2half2_rn(a.x, a.y);
        __half2 h1 = __floats2half2_rn(a.z, a.w);
        __half2 h2 = __floats2half2_rn(b.x, b.y);
        __half2 h3 = __floats2half2_rn(b.z, b.w);
        uint4 u;
        u.x = *(unsigned*)&h0; u.y = *(unsigned*)&h1;
        u.z = *(unsigned*)&h2; u.w = *(unsigned*)&h3;
        *(uint4*)&xh[i] = u;
    }
}

// ---------------- weight: row-normalize + convert to fp16 ----------------
__global__ void wnorm_half(const float* __restrict__ w, __half* __restrict__ wh, int K) {
    int r = blockIdx.x;
    const float* row = w + (size_t)r * K;
    float ss = 0.f;
    for (int c = threadIdx.x * 4; c < K; c += blockDim.x * 4) {
        float4 v = *(const float4*)(row + c);
        ss += v.x*v.x + v.y*v.y + v.z*v.z + v.w*v.w;
    }
    #pragma unroll
    for (int off = 16; off; off >>= 1) ss += __shfl_xor_sync(0xffffffffu, ss, off);
    __shared__ float sp[8];
    if ((threadIdx.x & 31) == 0) sp[threadIdx.x >> 5] = ss;
    __syncthreads();
    __shared__ float s_inv;
    if (threadIdx.x == 0) {
        float tot = 0.f;
        #pragma unroll
        for (int i = 0; i < 8; i++) tot += sp[i];
        s_inv = 1.f / (sqrtf(tot) + REPARAM_EPS);
    }
    __syncthreads();
    float inv = s_inv;
    for (int c = threadIdx.x * 4; c < K; c += blockDim.x * 4) {
        float4 v = *(const float4*)(row + c);
        __half2 h0 = __floats2half2_rn(v.x * inv, v.y * inv);
        __half2 h1 = __floats2half2_rn(v.z * inv, v.w * inv);
        uint2 u; u.x = *(unsigned*)&h0; u.y = *(unsigned*)&h1;
        *(uint2*)&wh[(size_t)r * K + c] = u;
    }
}

// ---------------- FP16 tensor-core GEMM: C[M,N](f32) = A[M,K] @ B[N,K]^T ----
// 128x128 tile, BK=64, 2-stage cp.async double buffer, 8 warps, warp 32x64.
#define GBK   64
#define GSTRH 72   // halves per smem row
#define GEMM_SMEM (2 * 2 * 128 * GSTRH * 2)   // 73728 bytes

__global__ __launch_bounds__(256, 2) void gemm_fp16(const __half* __restrict__ A,
                                                    const __half* __restrict__ B,
                                                    float* __restrict__ C,
                                                    int M, int N, int K) {
    extern __shared__ char smraw[];
    __half* As = (__half*)smraw;                 // [2][128][GSTRH]
    __half* Bs = As + 2 * 128 * GSTRH;
    unsigned asb = smem_u32(As), bsb = smem_u32(Bs);

    int tid = threadIdx.x, lane = tid & 31, wid = tid >> 5;
    int wm = wid & 3, wn = wid >> 2, g = lane >> 2, t = lane & 3;
    int bm = blockIdx.y * 128, bn = blockIdx.x * 128;

    float acc[2][8][4];
    #pragma unroll
    for (int mt = 0; mt < 2; mt++)
        #pragma unroll
        for (int nt = 0; nt < 8; nt++)
            #pragma unroll
            for (int i = 0; i < 4; i++) acc[mt][nt][i] = 0.f;

    auto issue = [&](int kb, int s) {
        int k0 = kb * GBK;
        #pragma unroll
        for (int i = 0; i < 4; i++) {
            int idx = tid + i * 256;
            int r = idx >> 3, c = idx & 7;
            cp16(asb + (s * 128 * GSTRH + r * GSTRH + c * 8) * 2,
                 A + (size_t)(bm + r) * K + k0 + c * 8);
            cp16(bsb + (s * 128 * GSTRH + r * GSTRH + c * 8) * 2,
                 B + (size_t)(bn + r) * K + k0 + c * 8);
        }
        CP_COMMIT();
    };

    int NIT = K / GBK;
    issue(0, 0);
    issue(1, 1);

    for (int kb = 0; kb < NIT; kb++) {
        CP_WAIT(1);
        __syncthreads();
        const __half* as = As + (kb & 1) * 128 * GSTRH;
        const __half* bs = Bs + (kb & 1) * 128 * GSTRH;
        #pragma unroll
        for (int ks = 0; ks < 4; ks++) {
            unsigned a[2][4];
            #pragma unroll
            for (int mt = 0; mt < 2; mt++) {
                int m = wm * 32 + mt * 16 + g;
                const unsigned* ap  = (const unsigned*)(as + m * GSTRH + ks * 16);
                const unsigned* ap8 = (const unsigned*)(as + (m + 8) * GSTRH + ks * 16);
                a[mt][0] = ap[t]; a[mt][1] = ap8[t];
                a[mt][2] = ap[t + 4]; a[mt][3] = ap8[t + 4];
            }
            #pragma unroll
            for (int nt = 0; nt < 8; nt++) {
                int n = wn * 64 + nt * 8 + g;
                const unsigned* bp = (const unsigned*)(bs + n * GSTRH + ks * 16);
                unsigned b0 = bp[t], b1 = bp[t + 4];
                mma16(acc[0][nt], a[0], b0, b1);
                mma16(acc[1][nt], a[1], b0, b1);
            }
        }
        __syncthreads();
        if (kb + 2 < NIT) issue(kb + 2, kb & 1); else CP_COMMIT();
    }

    #pragma unroll
    for (int mt = 0; mt < 2; mt++) {
        int r0 = bm + wm * 32 + mt * 16 + g;
        #pragma unroll
        for (int nt = 0; nt < 8; nt++) {
            int c = bn + wn * 64 + nt * 8 + 2 * t;
            *(float2*)&C[(size_t)r0 * N + c]       = make_float2(acc[mt][nt][0], acc[mt][nt][1]);
            *(float2*)&C[(size_t)(r0 + 8) * N + c] = make_float2(acc[mt][nt][2], acc[mt][nt][3]);
        }
    }
}

// ---------------- RoPE + l2norm + scale -> fp16 q/k, plus fp16 V copy -------
// grid (TOKENS, 6), block 256 = 4 heads x 64 threads. heads 0..15 q, 16..19 k, 20..23 v.
__global__ void rope_half(const float* __restrict__ qkv,
                          const float* __restrict__ fc,
                          const float* __restrict__ fs,
                          const float* __restrict__ s_q,
                          const float* __restrict__ s_k,
                          __half* __restrict__ qo,
                          __half* __restrict__ ko,
                          __half* __restrict__ vo) {
    int tok = blockIdx.x;
    int hsub = threadIdx.x >> 6;
    int i = threadIdx.x & 63;
    int h = blockIdx.y * 4 + hsub;
    int s = tok & (SEQLEN - 1);
    const float* base = qkv + (size_t)tok * QKV_OUT + h * HD;
    bool isv = (h >= 20);

    float orr = 0.f, oi = 0.f, ss = 0.f;
    float xr = base[2 * i], xi = base[2 * i + 1];
    if (!isv) {
        float c = fc[s * 64 + i], sn = fs[s * 64 + i];
        orr = xr * c - xi * sn;
        oi  = xr * sn + xi * c;
        ss = orr * orr + oi * oi;
    }
    #pragma unroll
    for (int off = 16; off; off >>= 1) ss += __shfl_xor_sync(0xffffffffu, ss, off);
    __shared__ float part[8];
    if ((threadIdx.x & 31) == 0) part[threadIdx.x >> 5] = ss;
    __syncthreads();

    if (isv) {
        *(__half2*)&vo[((size_t)tok * NKV + (h - 20)) * HD + 2 * i] =
            __floats2half2_rn(xr, xi);
    } else {
        float tot = part[hsub * 2] + part[hsub * 2 + 1];
        float inv = 1.f / (sqrtf(tot) + L2_EPS);
        const float* sc = (h < NH) ? s_q : s_k;
        __half2 o2 = __floats2half2_rn(orr * inv * sc[2 * i], oi * inv * sc[2 * i + 1]);
        if (h < NH)
            *(__half2*)&qo[((size_t)tok * NH + h) * HD + 2 * i] = o2;
        else
            *(__half2*)&ko[((size_t)tok * NKV + (h - NH)) * HD + 2 * i] = o2;
    }
}

// ---------------- FP16 flash attention ----------------
// grid (32, 16, 2), 256 threads, 8 warps (wm 0..3 x wn 0..1).
// BQ=64, BK=64. Warp: 16 q-rows, 32-key score split (wn), 64-d output split (wn).
#define KVSTR 136
#define PSTRH 72
#define FSMEM (((64 + 2*64 + 2*64) * KVSTR + 64 * PSTRH) * 2 + 2 * 2 * 64 * 4)

__global__ __launch_bounds__(256, 2) void flash_fp16(const __half* __restrict__ Qh,
                                                     const __half* __restrict__ Kh,
                                                     const __half* __restrict__ Vh,
                                                     const int* __restrict__ mask,
                                                     __half* __restrict__ Oh) {
    extern __shared__ char smraw[];
    __half* Qs  = (__half*)smraw;               // 64 x KVSTR
    __half* Ksm = Qs + 64 * KVSTR;              // 2 x 64 x KVSTR
    __half* Vsm = Ksm + 2 * 64 * KVSTR;         // 2 x 64 x KVSTR
    __half* Ps  = Vsm + 2 * 64 * KVSTR;         // 64 x PSTRH
    float* redm = (float*)(Ps + 64 * PSTRH);    // [2][64]
    float* reds = redm + 128;                   // [2][64]

    unsigned qsb = smem_u32(Qs), ksb = smem_u32(Ksm), vsb = smem_u32(Vsm);

    int tid = threadIdx.x, lane = tid & 31, wid = tid >> 5;
    int wm = wid & 3, wn = wid >> 2, g = lane >> 2, t = lane & 3;
    int lrow = lane & 15;
    int qb = blockIdx.x, h = blockIdx.y, b = blockIdx.z, hk = h >> 2;
    int q0 = qb * 64, qrow = wm * 16;
    const float scale = 11.313708498984761f;  // sqrt(128)

    auto issue_kv = [&](int kb, int s) {
        int k0 = kb * 64;
        #pragma unroll
        for (int i = 0; i < 4; i++) {
            int idx = tid + i * 256;
            int r = idx >> 4, c = idx & 15;
            size_t tok = (size_t)(b * SEQLEN + k0 + r);
            cp16(ksb + (s * 64 * KVSTR + r * KVSTR + c * 8) * 2,
                 Kh + (tok * NKV + hk) * HD + c * 8);
            cp16(vsb + (s * 64 * KVSTR + r * KVSTR + c * 8) * 2,
                 Vh + (tok * NKV + hk) * HD + c * 8);
        }
        CP_COMMIT();
    };

    // prologue: Q tile + first two KV stages
    #pragma unroll
    for (int i = 0; i < 4; i++) {
        int idx = tid + i * 256;
        int r = idx >> 4, c = idx & 15;
        cp16(qsb + (r * KVSTR + c * 8) * 2,
             Qh + ((size_t)(b * SEQLEN + q0 + r) * NH + h) * HD + c * 8);
    }
    CP_COMMIT();
    issue_kv(0, 0);
    issue_kv(1, 1);

    CP_WAIT(2);
    __syncthreads();

    // Q fragments in registers (persist across whole KV loop)
    unsigned qa[8][4];
    #pragma unroll
    for (int ks = 0; ks < 8; ks++) {
        const unsigned* qp  = (const unsigned*)(Qs + (qrow + g) * KVSTR + ks * 16);
        const unsigned* qp8 = (const unsigned*)(Qs + (qrow + g + 8) * KVSTR + ks * 16);
        qa[ks][0] = qp[t]; qa[ks][1] = qp8[t];
        qa[ks][2] = qp[t + 4]; qa[ks][3] = qp8[t + 4];
    }

    float o[8][4];
    #pragma unroll
    for (int nt = 0; nt < 8; nt++)
        #pragma unroll
        for (int i = 0; i < 4; i++) o[nt][i] = 0.f;
    float m0 = -1e30f, m1 = -1e30f, l0 = 0.f, l1 = 0.f;

    for (int kb = 0; kb < SEQLEN / 64; kb++) {
        int k0 = kb * 64;
        CP_WAIT(1);
        __syncthreads();
        const __half* ksm = Ksm + (kb & 1) * 64 * KVSTR;

        // ---- QK^T: 16 x 32 scores per warp ----
        float sc[4][4];
        #pragma unroll
        for (int nt = 0; nt < 4; nt++)
            #pragma unroll
            for (int i = 0; i < 4; i++) sc[nt][i] = 0.f;
        #pragma unroll
        for (int ks = 0; ks < 8; ks++) {
            #pragma unroll
            for (int nt = 0; nt < 4; nt++) {
                int n = wn * 32 + nt * 8 + g;
                const unsigned* bp = (const unsigned*)(ksm + n * KVSTR + ks * 16);
                mma16(sc[nt], qa[ks], bp[t], bp[t + 4]);
            }
        }
        // scale + mask bias
        #pragma unroll
        for (int nt = 0; nt < 4; nt++) {
            int col = k0 + wn * 32 + nt * 8 + 2 * t;
            float bb0 = mask[b * SEQLEN + col]     ? 0.f : -1e30f;
            float bb1 = mask[b * SEQLEN + col + 1] ? 0.f : -1e30f;
            sc[nt][0] = sc[nt][0] * scale + bb0;
            sc[nt][1] = sc[nt][1] * scale + bb1;
            sc[nt][2] = sc[nt][2] * scale + bb0;
            sc[nt][3] = sc[nt][3] * scale + bb1;
        }

        // ---- online softmax (pairwise warp exchange via named barrier) ----
        float mx0 = fmaxf(fmaxf(sc[0][0], sc[0][1]), fmaxf(sc[1][0], sc[1][1]));
        mx0 = fmaxf(mx0, fmaxf(fmaxf(sc[2][0], sc[2][1]), fmaxf(sc[3][0], sc[3][1])));
        float mx1 = fmaxf(fmaxf(sc[0][2], sc[0][3]), fmaxf(sc[1][2], sc[1][3]));
        mx1 = fmaxf(mx1, fmaxf(fmaxf(sc[2][2], sc[2][3]), fmaxf(sc[3][2], sc[3][3])));
        mx0 = fmaxf(mx0, __shfl_xor_sync(0xffffffffu, mx0, 1));
        mx0 = fmaxf(mx0, __shfl_xor_sync(0xffffffffu, mx0, 2));
        mx1 = fmaxf(mx1, __shfl_xor_sync(0xffffffffu, mx1, 1));
        mx1 = fmaxf(mx1, __shfl_xor_sync(0xffffffffu, mx1, 2));
        if (t == 0) {
            redm[wn * 64 + qrow + g] = mx0;
            redm[wn * 64 + qrow + g + 8] = mx1;
        }
        asm volatile("bar.sync %0, %1;" :: "r"(wm + 1), "r"(64) : "memory");
        float mn0 = fmaxf(m0, fmaxf(redm[qrow + g], redm[64 + qrow + g]));
        float mn1 = fmaxf(m1, fmaxf(redm[qrow + g + 8], redm[64 + qrow + g + 8]));
        float c0 = __expf(m0 - mn0), c1 = __expf(m1 - mn1);

        float s0 = 0.f, s1 = 0.f;
        #pragma unroll
        for (int nt = 0; nt < 4; nt++) {
            sc[nt][0] = __expf(sc[nt][0] - mn0);
            sc[nt][1] = __expf(sc[nt][1] - mn0);
            sc[nt][2] = __expf(sc[nt][2] - mn1);
            sc[nt][3] = __expf(sc[nt][3] - mn1);
            s0 += sc[nt][0] + sc[nt][1];
            s1 += sc[nt][2] + sc[nt][3];
        }
        s0 += __shfl_xor_sync(0xffffffffu, s0, 1);
        s0 += __shfl_xor_sync(0xffffffffu, s0, 2);
        s1 += __shfl_xor_sync(0xffffffffu, s1, 1);
        s1 += __shfl_xor_sync(0xffffffffu, s1, 2);
        if (t == 0) {
            reds[wn * 64 + qrow + g] = s0;
            reds[wn * 64 + qrow + g + 8] = s1;
        }
        // store P as half
        #pragma unroll
        for (int nt = 0; nt < 4; nt++) {
            int col = wn * 32 + nt * 8 + 2 * t;
            *(__half2*)&Ps[(qrow + g) * PSTRH + col]     = __floats2half2_rn(sc[nt][0], sc[nt][1]);
            *(__half2*)&Ps[(qrow + g + 8) * PSTRH + col] = __floats2half2_rn(sc[nt][2], sc[nt][3]);
        }
        asm volatile("bar.sync %0, %1;" :: "r"(wm + 1), "r"(64) : "memory");
        float ls0 = reds[qrow + g] + reds[64 + qrow + g];
        float ls1 = reds[qrow + g + 8] + reds[64 + qrow + g + 8];
        l0 = l0 * c0 + ls0;
        l1 = l1 * c1 + ls1;
        m0 = mn0; m1 = mn1;
        #pragma unroll
        for (int nt = 0; nt < 8; nt++) {
            o[nt][0] *= c0; o[nt][1] *= c0;
            o[nt][2] *= c1; o[nt][3] *= c1;
        }

        // ---- P @ V: 16 x 64 output per warp ----
        unsigned vstage = vsb + ((kb & 1) * 64 * KVSTR) * 2;
        #pragma unroll
        for (int ks = 0; ks < 4; ks++) {
            unsigned pa[4];
            const unsigned* pp  = (const unsigned*)(Ps + (qrow + g) * PSTRH + ks * 16);
            const unsigned* pp8 = (const unsigned*)(Ps + (qrow + g + 8) * PSTRH + ks * 16);
            pa[0] = pp[t]; pa[1] = pp8[t]; pa[2] = pp[t + 4]; pa[3] = pp8[t + 4];
            unsigned vrow = vstage + ((ks * 16 + lrow) * KVSTR) * 2;
            #pragma unroll
            for (int nt = 0; nt < 8; nt++) {
                unsigned addr = vrow + (wn * 64 + nt * 8) * 2;
                unsigned vb0, vb1;
                asm volatile("ldmatrix.sync.aligned.m8n8.x2.trans.shared.b16 {%0,%1},[%2];"
                             : "=r"(vb0), "=r"(vb1) : "r"(addr));
                mma16(o[nt], pa, vb0, vb1);
            }
        }
        __syncthreads();
        if (kb + 2 < SEQLEN / 64) issue_kv(kb + 2, kb & 1); else CP_COMMIT();
    }

    float i0 = 1.f / l0, i1 = 1.f / l1;
    #pragma unroll
    for (int nt = 0; nt < 8; nt++) {
        int col = h * HD + wn * 64 + nt * 8 + 2 * t;
        *(__half2*)&Oh[(size_t)(b * SEQLEN + q0 + qrow + g) * DIM + col] =
            __floats2half2_rn(o[nt][0] * i0, o[nt][1] * i0);
        *(__half2*)&Oh[(size_t)(b * SEQLEN + q0 + qrow + g + 8) * DIM + col] =
            __floats2half2_rn(o[nt][2] * i1, o[nt][3] * i1);
    }
}

// ---------------- launch ----------------
extern "C" void kernel_launch(void* const* d_in, const int* in_sizes, int n_in,
                              void* d_out, int out_size) {
    const float* x     = (const float*)d_in[0];
    const int*   mask  = (const int*)  d_in[1];
    const float* fc    = (const float*)d_in[2];
    const float* fs    = (const float*)d_in[3];
    const float* qkv_w = (const float*)d_in[4];
    const float* out_w = (const float*)d_in[5];
    const float* s_q   = (const float*)d_in[6];
    const float* s_k   = (const float*)d_in[7];
    float* out = (float*)d_out;

    void *p0, *p1, *p2, *p3, *p4, *p5, *p6, *p7;
    cudaGetSymbolAddress(&p0, g_qkv);
    cudaGetSymbolAddress(&p1, g_xh);
    cudaGetSymbolAddress(&p2, g_wqh);
    cudaGetSymbolAddress(&p3, g_woh);
    cudaGetSymbolAddress(&p4, g_qh);
    cudaGetSymbolAddress(&p5, g_kh);
    cudaGetSymbolAddress(&p6, g_vh);
    cudaGetSymbolAddress(&p7, g_attnh);
    float*  qkv   = (float*)p0;
    __half* xh    = (__half*)p1;
    __half* wqh   = (__half*)p2;
    __half* woh   = (__half*)p3;
    __half* qh    = (__half*)p4;
    __half* kh    = (__half*)p5;
    __half* vh    = (__half*)p6;
    __half* attnh = (__half*)p7;

    cudaFuncSetAttribute(gemm_fp16, cudaFuncAttributeMaxDynamicSharedMemorySize, GEMM_SMEM);
    cudaFuncSetAttribute(flash_fp16, cudaFuncAttributeMaxDynamicSharedMemorySize, FSMEM);

    // 1. operand conversions (fp16, weight norms folded in)
    f2h_kernel<<<TOKENS * DIM / 8 / 256, 256>>>(x, xh, TOKENS * DIM);
    wnorm_half<<<QKV_OUT, 256>>>(qkv_w, wqh, DIM);
    wnorm_half<<<DIM, 256>>>(out_w, woh, DIM);

    // 2. QKV projection (fp32 out, feeds rope)
    gemm_fp16<<<dim3(QKV_OUT / 128, TOKENS / 128), 256, GEMM_SMEM>>>(
        xh, wqh, qkv, TOKENS, QKV_OUT, DIM);

    // 3. RoPE + l2norm + scale -> fp16 q/k, fp16 v
    rope_half<<<dim3(TOKENS, 6), 256>>>(qkv, fc, fs, s_q, s_k, qh, kh, vh);

    // 4. flash attention (fp16 tensor cores) -> fp16 attn
    flash_fp16<<<dim3(SEQLEN / 64, NH, BSZ), 256, FSMEM>>>(qh, kh, vh, mask, attnh);

    // 5. output projection (fp32 out)
    gemm_fp16<<<dim3(DIM / 128, TOKENS / 128), 256, GEMM_SMEM>>>(
        attnh, woh, out, TOKENS, DIM, DIM);
}

// round 4
// speedup vs baseline: 28.9340x; 1.0816x over previous
#include <cuda_runtime.h>
#include <cuda_fp16.h>
#include <math.h>

// ---------------- problem constants ----------------
#define BSZ     2
#define SEQLEN  2048
#define DIM     2048
#define NH      16
#define NKV     4
#define HD      128
#define QKV_OUT 3072
#define TOKENS  (BSZ*SEQLEN)
#define REPARAM_EPS 1e-6f
#define L2_EPS      1e-12f

// ---------------- device scratch ----------------
__device__ float  g_qkv  [TOKENS * QKV_OUT];
__device__ __half g_xh   [TOKENS * DIM];
__device__ __half g_wqh  [QKV_OUT * DIM];
__device__ __half g_woh  [DIM * DIM];
__device__ __half g_qh   [TOKENS * NH  * HD];
__device__ __half g_kh   [TOKENS * NKV * HD];
__device__ __half g_vh   [TOKENS * NKV * HD];
__device__ __half g_attnh[TOKENS * DIM];

// ---------------- helpers ----------------
__device__ __forceinline__ void mma16(float* c, const unsigned* a, unsigned b0, unsigned b1) {
    asm volatile(
        "mma.sync.aligned.m16n8k16.row.col.f32.f16.f16.f32 "
        "{%0,%1,%2,%3},{%4,%5,%6,%7},{%8,%9},{%0,%1,%2,%3};"
        : "+f"(c[0]), "+f"(c[1]), "+f"(c[2]), "+f"(c[3])
        : "r"(a[0]), "r"(a[1]), "r"(a[2]), "r"(a[3]), "r"(b0), "r"(b1));
}
__device__ __forceinline__ unsigned smem_u32(const void* p) {
    return (unsigned)__cvta_generic_to_shared(p);
}
__device__ __forceinline__ void cp16(unsigned dst, const void* src) {
    asm volatile("cp.async.cg.shared.global [%0], [%1], 16;" :: "r"(dst), "l"(src));
}
#define CP_COMMIT() asm volatile("cp.async.commit_group;")
#define CP_WAIT(n)  asm volatile("cp.async.wait_group %0;" :: "n"(n))
#define LDSM4(r, addr) \
    asm volatile("ldmatrix.sync.aligned.m8n8.x4.shared.b16 {%0,%1,%2,%3},[%4];" \
        : "=r"((r)[0]), "=r"((r)[1]), "=r"((r)[2]), "=r"((r)[3]) : "r"(addr))
#define LDSM4T(r, addr) \
    asm volatile("ldmatrix.sync.aligned.m8n8.x4.trans.shared.b16 {%0,%1,%2,%3},[%4];" \
        : "=r"((r)[0]), "=r"((r)[1]), "=r"((r)[2]), "=r"((r)[3]) : "r"(addr))

__device__ __forceinline__ unsigned packh2(float x, float y) {
    __half2 h = __floats2half2_rn(x, y);
    return *(unsigned*)&h;
}

// ---------------- fp32 -> fp16 bulk convert ----------------
__global__ void f2h_kernel(const float* __restrict__ x, __half* __restrict__ xh, int n) {
    int i = (blockIdx.x * blockDim.x + threadIdx.x) * 8;
    if (i < n) {
        float4 a = *(const float4*)(x + i);
        float4 b = *(const float4*)(x + i + 4);
        uint4 u;
        u.x = packh2(a.x, a.y); u.y = packh2(a.z, a.w);
        u.z = packh2(b.x, b.y); u.w = packh2(b.z, b.w);
        *(uint4*)&xh[i] = u;
    }
}

// ---------------- weight: row-normalize + convert to fp16 ----------------
__global__ void wnorm_half(const float* __restrict__ w, __half* __restrict__ wh, int K) {
    int r = blockIdx.x;
    const float* row = w + (size_t)r * K;
    float ss = 0.f;
    for (int c = threadIdx.x * 4; c < K; c += blockDim.x * 4) {
        float4 v = *(const float4*)(row + c);
        ss += v.x*v.x + v.y*v.y + v.z*v.z + v.w*v.w;
    }
    #pragma unroll
    for (int off = 16; off; off >>= 1) ss += __shfl_xor_sync(0xffffffffu, ss, off);
    __shared__ float sp[8];
    if ((threadIdx.x & 31) == 0) sp[threadIdx.x >> 5] = ss;
    __syncthreads();
    __shared__ float s_inv;
    if (threadIdx.x == 0) {
        float tot = 0.f;
        #pragma unroll
        for (int i = 0; i < 8; i++) tot += sp[i];
        s_inv = 1.f / (sqrtf(tot) + REPARAM_EPS);
    }
    __syncthreads();
    float inv = s_inv;
    for (int c = threadIdx.x * 4; c < K; c += blockDim.x * 4) {
        float4 v = *(const float4*)(row + c);
        uint2 u;
        u.x = packh2(v.x * inv, v.y * inv);
        u.y = packh2(v.z * inv, v.w * inv);
        *(uint2*)&wh[(size_t)r * K + c] = u;
    }
}

// ---------------- FP16 tensor-core GEMM (ldmatrix-fed) ----------------
// C[M,N](f32) = A[M,K] @ B[N,K]^T. 128x128 tile, BK=64, 2-stage cp.async.
#define GBK   64
#define GSTRH 72
#define GEMM_SMEM (2 * 2 * 128 * GSTRH * 2)

__global__ __launch_bounds__(256, 2) void gemm_fp16(const __half* __restrict__ A,
                                                    const __half* __restrict__ B,
                                                    float* __restrict__ C,
                                                    int M, int N, int K) {
    extern __shared__ char smraw[];
    __half* As = (__half*)smraw;
    __half* Bs = As + 2 * 128 * GSTRH;
    unsigned asb = smem_u32(As), bsb = smem_u32(Bs);

    int tid = threadIdx.x, lane = tid & 31, wid = tid >> 5;
    int wm = wid & 3, wn = wid >> 2, g = lane >> 2, t = lane & 3;
    int bm = blockIdx.y * 128, bn = blockIdx.x * 128;

    // ldmatrix lane addressing
    int aRow = wm * 32 + ((lane >> 3) & 1) * 8 + (lane & 7);
    int aK   = ((lane >> 4) & 1) * 8;
    int bRow = wn * 64 + ((lane >> 4) & 1) * 8 + (lane & 7);
    int bK   = ((lane >> 3) & 1) * 8;
    unsigned aBase = asb + (aRow * GSTRH + aK) * 2;
    unsigned bBase = bsb + (bRow * GSTRH + bK) * 2;
    const unsigned STAGE = 128 * GSTRH * 2;

    float acc[2][8][4];
    #pragma unroll
    for (int mt = 0; mt < 2; mt++)
        #pragma unroll
        for (int nt = 0; nt < 8; nt++)
            #pragma unroll
            for (int i = 0; i < 4; i++) acc[mt][nt][i] = 0.f;

    auto issue = [&](int kb, int s) {
        int k0 = kb * GBK;
        #pragma unroll
        for (int i = 0; i < 4; i++) {
            int idx = tid + i * 256;
            int r = idx >> 3, c = idx & 7;
            cp16(asb + (s * 128 * GSTRH + r * GSTRH + c * 8) * 2,
                 A + (size_t)(bm + r) * K + k0 + c * 8);
            cp16(bsb + (s * 128 * GSTRH + r * GSTRH + c * 8) * 2,
                 B + (size_t)(bn + r) * K + k0 + c * 8);
        }
        CP_COMMIT();
    };

    int NIT = K / GBK;
    issue(0, 0);
    issue(1, 1);

    for (int kb = 0; kb < NIT; kb++) {
        CP_WAIT(1);
        __syncthreads();
        unsigned aoff = aBase + (kb & 1) * STAGE;
        unsigned boff = bBase + (kb & 1) * STAGE;
        #pragma unroll
        for (int ks = 0; ks < 4; ks++) {
            unsigned a0[4], a1[4];
            LDSM4(a0, aoff + ks * 32);
            LDSM4(a1, aoff + ks * 32 + 16 * GSTRH * 2);
            #pragma unroll
            for (int p = 0; p < 4; p++) {
                unsigned bb[4];
                LDSM4(bb, boff + ks * 32 + p * 16 * GSTRH * 2);
                mma16(acc[0][2*p],   a0, bb[0], bb[1]);
                mma16(acc[0][2*p+1], a0, bb[2], bb[3]);
                mma16(acc[1][2*p],   a1, bb[0], bb[1]);
                mma16(acc[1][2*p+1], a1, bb[2], bb[3]);
            }
        }
        __syncthreads();
        if (kb + 2 < NIT) issue(kb + 2, kb & 1); else CP_COMMIT();
    }

    #pragma unroll
    for (int mt = 0; mt < 2; mt++) {
        int r0 = bm + wm * 32 + mt * 16 + g;
        #pragma unroll
        for (int nt = 0; nt < 8; nt++) {
            int c = bn + wn * 64 + nt * 8 + 2 * t;
            *(float2*)&C[(size_t)r0 * N + c]       = make_float2(acc[mt][nt][0], acc[mt][nt][1]);
            *(float2*)&C[(size_t)(r0 + 8) * N + c] = make_float2(acc[mt][nt][2], acc[mt][nt][3]);
        }
    }
}

// ---------------- RoPE + l2norm + scale -> fp16 q/k/v -------
__global__ void rope_half(const float* __restrict__ qkv,
                          const float* __restrict__ fc,
                          const float* __restrict__ fs,
                          const float* __restrict__ s_q,
                          const float* __restrict__ s_k,
                          __half* __restrict__ qo,
                          __half* __restrict__ ko,
                          __half* __restrict__ vo) {
    int tok = blockIdx.x;
    int hsub = threadIdx.x >> 6;
    int i = threadIdx.x & 63;
    int h = blockIdx.y * 4 + hsub;
    int s = tok & (SEQLEN - 1);
    const float* base = qkv + (size_t)tok * QKV_OUT + h * HD;
    bool isv = (h >= 20);

    float orr = 0.f, oi = 0.f, ss = 0.f;
    float xr = base[2 * i], xi = base[2 * i + 1];
    if (!isv) {
        float c = fc[s * 64 + i], sn = fs[s * 64 + i];
        orr = xr * c - xi * sn;
        oi  = xr * sn + xi * c;
        ss = orr * orr + oi * oi;
    }
    #pragma unroll
    for (int off = 16; off; off >>= 1) ss += __shfl_xor_sync(0xffffffffu, ss, off);
    __shared__ float part[8];
    if ((threadIdx.x & 31) == 0) part[threadIdx.x >> 5] = ss;
    __syncthreads();

    if (isv) {
        *(__half2*)&vo[((size_t)tok * NKV + (h - 20)) * HD + 2 * i] =
            __floats2half2_rn(xr, xi);
    } else {
        float tot = part[hsub * 2] + part[hsub * 2 + 1];
        float inv = 1.f / (sqrtf(tot) + L2_EPS);
        const float* sc = (h < NH) ? s_q : s_k;
        __half2 o2 = __floats2half2_rn(orr * inv * sc[2 * i], oi * inv * sc[2 * i + 1]);
        if (h < NH)
            *(__half2*)&qo[((size_t)tok * NH + h) * HD + 2 * i] = o2;
        else
            *(__half2*)&ko[((size_t)tok * NKV + (h - NH)) * HD + 2 * i] = o2;
    }
}

// ---------------- FP16 flash attention, register-resident P ----------------
// grid (16, 16, 2), 256 threads = 8 warps. BQ=128, BK=64.
// Warp w: q-rows w*16..w*16+15, all 64 keys, all 128 d. No inter-warp exchange.
#define KVSTR 136
#define FSMEM ((128 * KVSTR + 2 * 64 * KVSTR * 2) * 2)

__global__ __launch_bounds__(256, 1) void flash_fp16(const __half* __restrict__ Qh,
                                                     const __half* __restrict__ Kh,
                                                     const __half* __restrict__ Vh,
                                                     const int* __restrict__ mask,
                                                     __half* __restrict__ Oh) {
    extern __shared__ char smraw[];
    __half* Qs  = (__half*)smraw;                // 128 x KVSTR (prologue only)
    __half* Ksm = Qs + 128 * KVSTR;              // 2 x 64 x KVSTR
    __half* Vsm = Ksm + 2 * 64 * KVSTR;          // 2 x 64 x KVSTR
    unsigned qsb = smem_u32(Qs), ksb = smem_u32(Ksm), vsb = smem_u32(Vsm);

    int tid = threadIdx.x, lane = tid & 31, wid = tid >> 5;
    int g = lane >> 2, t = lane & 3;
    int qb = blockIdx.x, h = blockIdx.y, b = blockIdx.z, hk = h >> 2;
    int q0 = qb * 128, qrow0 = wid * 16;
    const float scale = 11.313708498984761f;   // sqrt(128)
    const unsigned KVSTAGE = 64 * KVSTR * 2;

    auto issue_kv = [&](int kb, int s) {
        int k0 = kb * 64;
        #pragma unroll
        for (int i = 0; i < 4; i++) {
            int idx = tid + i * 256;
            int r = idx >> 4, c = idx & 15;
            size_t tok = (size_t)(b * SEQLEN + k0 + r);
            cp16(ksb + s * KVSTAGE + (r * KVSTR + c * 8) * 2,
                 Kh + (tok * NKV + hk) * HD + c * 8);
            cp16(vsb + s * KVSTAGE + (r * KVSTR + c * 8) * 2,
                 Vh + (tok * NKV + hk) * HD + c * 8);
        }
        CP_COMMIT();
    };

    // prologue: Q tile (128 rows)
    #pragma unroll
    for (int i = 0; i < 8; i++) {
        int idx = tid + i * 256;
        int r = idx >> 4, c = idx & 15;
        cp16(qsb + (r * KVSTR + c * 8) * 2,
             Qh + ((size_t)(b * SEQLEN + q0 + r) * NH + h) * HD + c * 8);
    }
    CP_COMMIT();
    issue_kv(0, 0);
    issue_kv(1, 1);

    CP_WAIT(2);
    __syncthreads();

    // Q fragments -> registers (persist for whole KV loop)
    unsigned qa[8][4];
    {
        int qr = qrow0 + ((lane >> 3) & 1) * 8 + (lane & 7);
        int qk = ((lane >> 4) & 1) * 8;
        unsigned qaddr = qsb + (qr * KVSTR + qk) * 2;
        #pragma unroll
        for (int ks = 0; ks < 8; ks++) LDSM4(qa[ks], qaddr + ks * 32);
    }

    float o[16][4];
    #pragma unroll
    for (int nt = 0; nt < 16; nt++)
        #pragma unroll
        for (int i = 0; i < 4; i++) o[nt][i] = 0.f;
    float m0 = -1e30f, m1 = -1e30f, l0 = 0.f, l1 = 0.f;

    // per-lane ldmatrix addressing (K: non-trans, V: trans)
    int kRow = ((lane >> 4) & 1) * 8 + (lane & 7);
    int kK   = ((lane >> 3) & 1) * 8;
    int vRow = lane & 15;
    int vD   = ((lane >> 4) & 1) * 8;

    for (int kb = 0; kb < SEQLEN / 64; kb++) {
        int k0 = kb * 64;
        CP_WAIT(1);
        __syncthreads();
        unsigned kbase = ksb + (kb & 1) * KVSTAGE + (kRow * KVSTR + kK) * 2;
        unsigned vbase = vsb + (kb & 1) * KVSTAGE + (vRow * KVSTR + vD) * 2;

        // ---- QK^T: 16 x 64 scores per warp ----
        float sc[8][4];
        #pragma unroll
        for (int nt = 0; nt < 8; nt++)
            #pragma unroll
            for (int i = 0; i < 4; i++) sc[nt][i] = 0.f;
        #pragma unroll
        for (int ks = 0; ks < 8; ks++) {
            #pragma unroll
            for (int p = 0; p < 4; p++) {
                unsigned bb[4];
                LDSM4(bb, kbase + p * 16 * KVSTR * 2 + ks * 32);
                mma16(sc[2*p],   qa[ks], bb[0], bb[1]);
                mma16(sc[2*p+1], qa[ks], bb[2], bb[3]);
            }
        }
        // scale + mask bias
        #pragma unroll
        for (int nt = 0; nt < 8; nt++) {
            int2 mm = *(const int2*)&mask[b * SEQLEN + k0 + nt * 8 + 2 * t];
            float bb0 = mm.x ? 0.f : -1e30f;
            float bb1 = mm.y ? 0.f : -1e30f;
            sc[nt][0] = sc[nt][0] * scale + bb0;
            sc[nt][1] = sc[nt][1] * scale + bb1;
            sc[nt][2] = sc[nt][2] * scale + bb0;
            sc[nt][3] = sc[nt][3] * scale + bb1;
        }

        // ---- warp-local online softmax ----
        float mx0 = -1e30f, mx1 = -1e30f;
        #pragma unroll
        for (int nt = 0; nt < 8; nt++) {
            mx0 = fmaxf(mx0, fmaxf(sc[nt][0], sc[nt][1]));
            mx1 = fmaxf(mx1, fmaxf(sc[nt][2], sc[nt][3]));
        }
        mx0 = fmaxf(mx0, __shfl_xor_sync(0xffffffffu, mx0, 1));
        mx0 = fmaxf(mx0, __shfl_xor_sync(0xffffffffu, mx0, 2));
        mx1 = fmaxf(mx1, __shfl_xor_sync(0xffffffffu, mx1, 1));
        mx1 = fmaxf(mx1, __shfl_xor_sync(0xffffffffu, mx1, 2));
        float mn0 = fmaxf(m0, mx0), mn1 = fmaxf(m1, mx1);
        float c0 = __expf(m0 - mn0), c1 = __expf(m1 - mn1);

        float s0 = 0.f, s1 = 0.f;
        #pragma unroll
        for (int nt = 0; nt < 8; nt++) {
            sc[nt][0] = __expf(sc[nt][0] - mn0);
            sc[nt][1] = __expf(sc[nt][1] - mn0);
            sc[nt][2] = __expf(sc[nt][2] - mn1);
            sc[nt][3] = __expf(sc[nt][3] - mn1);
            s0 += sc[nt][0] + sc[nt][1];
            s1 += sc[nt][2] + sc[nt][3];
        }
        s0 += __shfl_xor_sync(0xffffffffu, s0, 1);
        s0 += __shfl_xor_sync(0xffffffffu, s0, 2);
        s1 += __shfl_xor_sync(0xffffffffu, s1, 1);
        s1 += __shfl_xor_sync(0xffffffffu, s1, 2);
        l0 = l0 * c0 + s0;
        l1 = l1 * c1 + s1;
        m0 = mn0; m1 = mn1;
        #pragma unroll
        for (int nt = 0; nt < 16; nt++) {
            o[nt][0] *= c0; o[nt][1] *= c0;
            o[nt][2] *= c1; o[nt][3] *= c1;
        }

        // ---- P @ V with register-resident P (C-frag == A-frag layout) ----
        #pragma unroll
        for (int j = 0; j < 4; j++) {
            unsigned pa[4];
            pa[0] = packh2(sc[2*j][0],   sc[2*j][1]);
            pa[1] = packh2(sc[2*j][2],   sc[2*j][3]);
            pa[2] = packh2(sc[2*j+1][0], sc[2*j+1][1]);
            pa[3] = packh2(sc[2*j+1][2], sc[2*j+1][3]);
            unsigned vrow = vbase + j * 16 * KVSTR * 2;
            #pragma unroll
            for (int p = 0; p < 8; p++) {
                unsigned vb[4];
                LDSM4T(vb, vrow + p * 32);
                mma16(o[2*p],   pa, vb[0], vb[1]);
                mma16(o[2*p+1], pa, vb[2], vb[3]);
            }
        }
        __syncthreads();
        if (kb + 2 < SEQLEN / 64) issue_kv(kb + 2, kb & 1); else CP_COMMIT();
    }

    float i0 = 1.f / l0, i1 = 1.f / l1;
    size_t r0 = (size_t)(b * SEQLEN + q0 + qrow0 + g) * DIM;
    size_t r1 = r0 + 8 * DIM;
    #pragma unroll
    for (int nt = 0; nt < 16; nt++) {
        int col = h * HD + nt * 8 + 2 * t;
        *(__half2*)&Oh[r0 + col] = __floats2half2_rn(o[nt][0] * i0, o[nt][1] * i0);
        *(__half2*)&Oh[r1 + col] = __floats2half2_rn(o[nt][2] * i1, o[nt][3] * i1);
    }
}

// ---------------- launch ----------------
extern "C" void kernel_launch(void* const* d_in, const int* in_sizes, int n_in,
                              void* d_out, int out_size) {
    const float* x     = (const float*)d_in[0];
    const int*   mask  = (const int*)  d_in[1];
    const float* fc    = (const float*)d_in[2];
    const float* fs    = (const float*)d_in[3];
    const float* qkv_w = (const float*)d_in[4];
    const float* out_w = (const float*)d_in[5];
    const float* s_q   = (const float*)d_in[6];
    const float* s_k   = (const float*)d_in[7];
    float* out = (float*)d_out;

    void *p0, *p1, *p2, *p3, *p4, *p5, *p6, *p7;
    cudaGetSymbolAddress(&p0, g_qkv);
    cudaGetSymbolAddress(&p1, g_xh);
    cudaGetSymbolAddress(&p2, g_wqh);
    cudaGetSymbolAddress(&p3, g_woh);
    cudaGetSymbolAddress(&p4, g_qh);
    cudaGetSymbolAddress(&p5, g_kh);
    cudaGetSymbolAddress(&p6, g_vh);
    cudaGetSymbolAddress(&p7, g_attnh);
    float*  qkv   = (float*)p0;
    __half* xh    = (__half*)p1;
    __half* wqh   = (__half*)p2;
    __half* woh   = (__half*)p3;
    __half* qh    = (__half*)p4;
    __half* kh    = (__half*)p5;
    __half* vh    = (__half*)p6;
    __half* attnh = (__half*)p7;

    cudaFuncSetAttribute(gemm_fp16, cudaFuncAttributeMaxDynamicSharedMemorySize, GEMM_SMEM);
    cudaFuncSetAttribute(flash_fp16, cudaFuncAttributeMaxDynamicSharedMemorySize, FSMEM);

    f2h_kernel<<<TOKENS * DIM / 8 / 256, 256>>>(x, xh, TOKENS * DIM);
    wnorm_half<<<QKV_OUT, 256>>>(qkv_w, wqh, DIM);
    wnorm_half<<<DIM, 256>>>(out_w, woh, DIM);

    gemm_fp16<<<dim3(QKV_OUT / 128, TOKENS / 128), 256, GEMM_SMEM>>>(
        xh, wqh, qkv, TOKENS, QKV_OUT, DIM);

    rope_half<<<dim3(TOKENS, 6), 256>>>(qkv, fc, fs, s_q, s_k, qh, kh, vh);

    flash_fp16<<<dim3(SEQLEN / 128, NH, BSZ), 256, FSMEM>>>(qh, kh, vh, mask, attnh);

    gemm_fp16<<<dim3(DIM / 128, TOKENS / 128), 256, GEMM_SMEM>>>(
        attnh, woh, out, TOKENS, DIM, DIM);
}

// round 6
// speedup vs baseline: 29.6946x; 1.0263x over previous
#include <cuda_runtime.h>
#include <cuda_fp16.h>
#include <math.h>
#include <cstdint>

// ---------------- problem constants ----------------
#define BSZ     2
#define SEQLEN  2048
#define DIM     2048
#define NH      16
#define NKV     4
#define HD      128
#define QKV_OUT 3072
#define TOKENS  (BSZ*SEQLEN)
#define REPARAM_EPS 1e-6f
#define L2_EPS      1e-12f

// ---------------- device scratch ----------------
__device__ float  g_qkv  [TOKENS * QKV_OUT];
__device__ __half g_xh   [TOKENS * DIM];
__device__ __half g_wqh  [QKV_OUT * DIM];
__device__ __half g_woh  [DIM * DIM];
__device__ __half g_qh   [TOKENS * NH  * HD];
__device__ __half g_kh   [TOKENS * NKV * HD];
__device__ __half g_vh   [TOKENS * NKV * HD];
__device__ __half g_attnh[TOKENS * DIM];

// ---------------- helpers ----------------
__device__ __forceinline__ void mma16(float* c, const unsigned* a, unsigned b0, unsigned b1) {
    asm volatile(
        "mma.sync.aligned.m16n8k16.row.col.f32.f16.f16.f32 "
        "{%0,%1,%2,%3},{%4,%5,%6,%7},{%8,%9},{%0,%1,%2,%3};"
        : "+f"(c[0]), "+f"(c[1]), "+f"(c[2]), "+f"(c[3])
        : "r"(a[0]), "r"(a[1]), "r"(a[2]), "r"(a[3]), "r"(b0), "r"(b1));
}
__device__ __forceinline__ unsigned smem_u32(const void* p) {
    return (unsigned)__cvta_generic_to_shared(p);
}
__device__ __forceinline__ void cp16(unsigned dst, const void* src) {
    asm volatile("cp.async.cg.shared.global [%0], [%1], 16;" :: "r"(dst), "l"(src));
}
#define CP_COMMIT() asm volatile("cp.async.commit_group;")
#define CP_WAIT(n)  asm volatile("cp.async.wait_group %0;" :: "n"(n))
#define LDSM4(r, addr) \
    asm volatile("ldmatrix.sync.aligned.m8n8.x4.shared.b16 {%0,%1,%2,%3},[%4];" \
        : "=r"((r)[0]), "=r"((r)[1]), "=r"((r)[2]), "=r"((r)[3]) : "r"(addr))
#define LDSM4T(r, addr) \
    asm volatile("ldmatrix.sync.aligned.m8n8.x4.trans.shared.b16 {%0,%1,%2,%3},[%4];" \
        : "=r"((r)[0]), "=r"((r)[1]), "=r"((r)[2]), "=r"((r)[3]) : "r"(addr))
__device__ __forceinline__ unsigned packh2(float x, float y) {
    __half2 h = __floats2half2_rn(x, y);
    return *(unsigned*)&h;
}

// ---------------- fp32 -> fp16 bulk convert ----------------
__global__ void f2h_kernel(const float* __restrict__ x, __half* __restrict__ xh, int n) {
    int i = (blockIdx.x * blockDim.x + threadIdx.x) * 8;
    if (i < n) {
        float4 a = *(const float4*)(x + i);
        float4 b = *(const float4*)(x + i + 4);
        uint4 u;
        u.x = packh2(a.x, a.y); u.y = packh2(a.z, a.w);
        u.z = packh2(b.x, b.y); u.w = packh2(b.z, b.w);
        *(uint4*)&xh[i] = u;
    }
}

// ---------------- weight: row-normalize + convert to fp16 ----------------
__global__ void wnorm_half(const float* __restrict__ w, __half* __restrict__ wh, int K) {
    int r = blockIdx.x;
    const float* row = w + (size_t)r * K;
    float ss = 0.f;
    for (int c = threadIdx.x * 4; c < K; c += blockDim.x * 4) {
        float4 v = *(const float4*)(row + c);
        ss += v.x*v.x + v.y*v.y + v.z*v.z + v.w*v.w;
    }
    #pragma unroll
    for (int off = 16; off; off >>= 1) ss += __shfl_xor_sync(0xffffffffu, ss, off);
    __shared__ float sp[8];
    if ((threadIdx.x & 31) == 0) sp[threadIdx.x >> 5] = ss;
    __syncthreads();
    __shared__ float s_inv;
    if (threadIdx.x == 0) {
        float tot = 0.f;
        #pragma unroll
        for (int i = 0; i < 8; i++) tot += sp[i];
        s_inv = 1.f / (sqrtf(tot) + REPARAM_EPS);
    }
    __syncthreads();
    float inv = s_inv;
    for (int c = threadIdx.x * 4; c < K; c += blockDim.x * 4) {
        float4 v = *(const float4*)(row + c);
        uint2 u;
        u.x = packh2(v.x * inv, v.y * inv);
        u.y = packh2(v.z * inv, v.w * inv);
        *(uint2*)&wh[(size_t)r * K + c] = u;
    }
}

// ---------------- FP16 tensor-core GEMM, 3-stage, 1 barrier/iter ----------
// C[M,N](f32) = A[M,K] @ B[N,K]^T. 128x128 tile, BK=64.
#define GBK    64
#define GSTRH  72
#define GSTAGE (128 * GSTRH)               // halves per matrix per stage
#define GEMM_SMEM (3 * 2 * GSTAGE * 2)     // 110592 bytes

__global__ __launch_bounds__(256, 2) void gemm_fp16(const __half* __restrict__ A,
                                                    const __half* __restrict__ B,
                                                    float* __restrict__ C,
                                                    int M, int N, int K) {
    extern __shared__ char smraw[];
    __half* As = (__half*)smraw;                 // [3][128][GSTRH]
    __half* Bs = As + 3 * GSTAGE;
    unsigned asb = smem_u32(As), bsb = smem_u32(Bs);

    int tid = threadIdx.x, lane = tid & 31, wid = tid >> 5;
    int wm = wid & 3, wn = wid >> 2, g = lane >> 2, t = lane & 3;
    int bm = blockIdx.y * 128, bn = blockIdx.x * 128;

    int aRow = wm * 32 + ((lane >> 3) & 1) * 8 + (lane & 7);
    int aK   = ((lane >> 4) & 1) * 8;
    int bRow = wn * 64 + ((lane >> 4) & 1) * 8 + (lane & 7);
    int bK   = ((lane >> 3) & 1) * 8;
    unsigned aBase = asb + (aRow * GSTRH + aK) * 2;
    unsigned bBase = bsb + (bRow * GSTRH + bK) * 2;
    const unsigned STAGE = GSTAGE * 2;

    float acc[2][8][4];
    #pragma unroll
    for (int mt = 0; mt < 2; mt++)
        #pragma unroll
        for (int nt = 0; nt < 8; nt++)
            #pragma unroll
            for (int i = 0; i < 4; i++) acc[mt][nt][i] = 0.f;

    auto issue = [&](int kb, int s) {
        int k0 = kb * GBK;
        #pragma unroll
        for (int i = 0; i < 4; i++) {
            int idx = tid + i * 256;
            int r = idx >> 3, c = idx & 7;
            cp16(asb + (s * GSTAGE + r * GSTRH + c * 8) * 2,
                 A + (size_t)(bm + r) * K + k0 + c * 8);
            cp16(bsb + (s * GSTAGE + r * GSTRH + c * 8) * 2,
                 B + (size_t)(bn + r) * K + k0 + c * 8);
        }
        CP_COMMIT();
    };

    int NIT = K / GBK;
    issue(0, 0);
    issue(1, 1);

    int srd = 0, swr = 2;
    for (int kb = 0; kb < NIT; kb++) {
        CP_WAIT(1);
        __syncthreads();
        if (kb + 2 < NIT) issue(kb + 2, swr); else CP_COMMIT();
        unsigned aoff = aBase + srd * STAGE;
        unsigned boff = bBase + srd * STAGE;
        #pragma unroll
        for (int ks = 0; ks < 4; ks++) {
            unsigned a0[4], a1[4];
            LDSM4(a0, aoff + ks * 32);
            LDSM4(a1, aoff + ks * 32 + 16 * GSTRH * 2);
            #pragma unroll
            for (int p = 0; p < 4; p++) {
                unsigned bb[4];
                LDSM4(bb, boff + ks * 32 + p * 16 * GSTRH * 2);
                mma16(acc[0][2*p],   a0, bb[0], bb[1]);
                mma16(acc[0][2*p+1], a0, bb[2], bb[3]);
                mma16(acc[1][2*p],   a1, bb[0], bb[1]);
                mma16(acc[1][2*p+1], a1, bb[2], bb[3]);
            }
        }
        srd = (srd == 2) ? 0 : srd + 1;
        swr = (swr == 2) ? 0 : swr + 1;
    }

    #pragma unroll
    for (int mt = 0; mt < 2; mt++) {
        int r0 = bm + wm * 32 + mt * 16 + g;
        #pragma unroll
        for (int nt = 0; nt < 8; nt++) {
            int c = bn + wn * 64 + nt * 8 + 2 * t;
            *(float2*)&C[(size_t)r0 * N + c]       = make_float2(acc[mt][nt][0], acc[mt][nt][1]);
            *(float2*)&C[(size_t)(r0 + 8) * N + c] = make_float2(acc[mt][nt][2], acc[mt][nt][3]);
        }
    }
}

// ---------------- RoPE + l2norm + scale -> fp16 q/k/v (warp-per-head) -------
// grid (TOKENS), 256 threads = 8 warps. Warp w handles heads w, w+8, w+16.
__global__ void rope_half(const float* __restrict__ qkv,
                          const float* __restrict__ fc,
                          const float* __restrict__ fs,
                          const float* __restrict__ s_q,
                          const float* __restrict__ s_k,
                          __half* __restrict__ qo,
                          __half* __restrict__ ko,
                          __half* __restrict__ vo) {
    int tok = blockIdx.x;
    int lane = threadIdx.x & 31, w = threadIdx.x >> 5;
    int s = tok & (SEQLEN - 1);
    #pragma unroll
    for (int hh = 0; hh < 3; hh++) {
        int h = w + hh * 8;
        const float* base = qkv + (size_t)tok * QKV_OUT + h * HD;
        float2 v0 = *(const float2*)(base + 2 * lane);
        float2 v1 = *(const float2*)(base + 2 * (lane + 32));
        if (h >= 20) {
            __half* dst = &vo[((size_t)tok * NKV + (h - 20)) * HD];
            *(__half2*)&dst[2 * lane]        = __floats2half2_rn(v0.x, v0.y);
            *(__half2*)&dst[2 * (lane + 32)] = __floats2half2_rn(v1.x, v1.y);
        } else {
            float c0 = fc[s * 64 + lane],      sn0 = fs[s * 64 + lane];
            float c1 = fc[s * 64 + lane + 32], sn1 = fs[s * 64 + lane + 32];
            float r0 = v0.x * c0 - v0.y * sn0, i0 = v0.x * sn0 + v0.y * c0;
            float r1 = v1.x * c1 - v1.y * sn1, i1 = v1.x * sn1 + v1.y * c1;
            float ss = r0 * r0 + i0 * i0 + r1 * r1 + i1 * i1;
            #pragma unroll
            for (int off = 16; off; off >>= 1) ss += __shfl_xor_sync(0xffffffffu, ss, off);
            float inv = 1.f / (sqrtf(ss) + L2_EPS);
            const float* sc = (h < NH) ? s_q : s_k;
            __half* dst = (h < NH) ? &qo[((size_t)tok * NH + h) * HD]
                                   : &ko[((size_t)tok * NKV + (h - NH)) * HD];
            *(__half2*)&dst[2 * lane] =
                __floats2half2_rn(r0 * inv * sc[2 * lane], i0 * inv * sc[2 * lane + 1]);
            *(__half2*)&dst[2 * (lane + 32)] =
                __floats2half2_rn(r1 * inv * sc[2 * (lane + 32)], i1 * inv * sc[2 * (lane + 32) + 1]);
        }
    }
}

// ---------------- FP16 flash attention, 3-stage KV, 1 barrier/iter ----------
#define KVSTR 136
#define KVST  (64 * KVSTR)                 // halves per matrix per stage
#define FSMEM ((128 * KVSTR + 3 * KVST * 2) * 2)

__global__ __launch_bounds__(256, 1) void flash_fp16(const __half* __restrict__ Qh,
                                                     const __half* __restrict__ Kh,
                                                     const __half* __restrict__ Vh,
                                                     const int* __restrict__ mask,
                                                     __half* __restrict__ Oh) {
    extern __shared__ char smraw[];
    __half* Qs  = (__half*)smraw;                // 128 x KVSTR
    __half* Ksm = Qs + 128 * KVSTR;              // 3 x 64 x KVSTR
    __half* Vsm = Ksm + 3 * KVST;                // 3 x 64 x KVSTR
    unsigned qsb = smem_u32(Qs), ksb = smem_u32(Ksm), vsb = smem_u32(Vsm);

    int tid = threadIdx.x, lane = tid & 31, wid = tid >> 5;
    int g = lane >> 2, t = lane & 3;
    int qb = blockIdx.x, h = blockIdx.y, b = blockIdx.z, hk = h >> 2;
    int q0 = qb * 128, qrow0 = wid * 16;
    const float scale = 11.313708498984761f;
    const unsigned KVSTAGE = KVST * 2;

    auto issue_kv = [&](int kb, int s) {
        int k0 = kb * 64;
        #pragma unroll
        for (int i = 0; i < 4; i++) {
            int idx = tid + i * 256;
            int r = idx >> 4, c = idx & 15;
            size_t tok = (size_t)(b * SEQLEN + k0 + r);
            cp16(ksb + s * KVSTAGE + (r * KVSTR + c * 8) * 2,
                 Kh + (tok * NKV + hk) * HD + c * 8);
            cp16(vsb + s * KVSTAGE + (r * KVSTR + c * 8) * 2,
                 Vh + (tok * NKV + hk) * HD + c * 8);
        }
        CP_COMMIT();
    };

    #pragma unroll
    for (int i = 0; i < 8; i++) {
        int idx = tid + i * 256;
        int r = idx >> 4, c = idx & 15;
        cp16(qsb + (r * KVSTR + c * 8) * 2,
             Qh + ((size_t)(b * SEQLEN + q0 + r) * NH + h) * HD + c * 8);
    }
    CP_COMMIT();
    issue_kv(0, 0);
    issue_kv(1, 1);

    CP_WAIT(2);
    __syncthreads();

    unsigned qa[8][4];
    {
        int qr = qrow0 + ((lane >> 3) & 1) * 8 + (lane & 7);
        int qk = ((lane >> 4) & 1) * 8;
        unsigned qaddr = qsb + (qr * KVSTR + qk) * 2;
        #pragma unroll
        for (int ks = 0; ks < 8; ks++) LDSM4(qa[ks], qaddr + ks * 32);
    }

    float o[16][4];
    #pragma unroll
    for (int nt = 0; nt < 16; nt++)
        #pragma unroll
        for (int i = 0; i < 4; i++) o[nt][i] = 0.f;
    float m0 = -1e30f, m1 = -1e30f, l0 = 0.f, l1 = 0.f;

    int kRow = ((lane >> 4) & 1) * 8 + (lane & 7);
    int kK   = ((lane >> 3) & 1) * 8;
    int vRow = lane & 15;
    int vD   = ((lane >> 4) & 1) * 8;

    int srd = 0, swr = 2;
    for (int kb = 0; kb < SEQLEN / 64; kb++) {
        int k0 = kb * 64;
        CP_WAIT(1);
        __syncthreads();
        if (kb + 2 < SEQLEN / 64) issue_kv(kb + 2, swr); else CP_COMMIT();
        unsigned kbase = ksb + srd * KVSTAGE + (kRow * KVSTR + kK) * 2;
        unsigned vbase = vsb + srd * KVSTAGE + (vRow * KVSTR + vD) * 2;

        float sc[8][4];
        #pragma unroll
        for (int nt = 0; nt < 8; nt++)
            #pragma unroll
            for (int i = 0; i < 4; i++) sc[nt][i] = 0.f;
        #pragma unroll
        for (int ks = 0; ks < 8; ks++) {
            #pragma unroll
            for (int p = 0; p < 4; p++) {
                unsigned bb[4];
                LDSM4(bb, kbase + p * 16 * KVSTR * 2 + ks * 32);
                mma16(sc[2*p],   qa[ks], bb[0], bb[1]);
                mma16(sc[2*p+1], qa[ks], bb[2], bb[3]);
            }
        }
        #pragma unroll
        for (int nt = 0; nt < 8; nt++) {
            int2 mm = *(const int2*)&mask[b * SEQLEN + k0 + nt * 8 + 2 * t];
            float bb0 = mm.x ? 0.f : -1e30f;
            float bb1 = mm.y ? 0.f : -1e30f;
            sc[nt][0] = sc[nt][0] * scale + bb0;
            sc[nt][1] = sc[nt][1] * scale + bb1;
            sc[nt][2] = sc[nt][2] * scale + bb0;
            sc[nt][3] = sc[nt][3] * scale + bb1;
        }

        float mx0 = -1e30f, mx1 = -1e30f;
        #pragma unroll
        for (int nt = 0; nt < 8; nt++) {
            mx0 = fmaxf(mx0, fmaxf(sc[nt][0], sc[nt][1]));
            mx1 = fmaxf(mx1, fmaxf(sc[nt][2], sc[nt][3]));
        }
        mx0 = fmaxf(mx0, __shfl_xor_sync(0xffffffffu, mx0, 1));
        mx0 = fmaxf(mx0, __shfl_xor_sync(0xffffffffu, mx0, 2));
        mx1 = fmaxf(mx1, __shfl_xor_sync(0xffffffffu, mx1, 1));
        mx1 = fmaxf(mx1, __shfl_xor_sync(0xffffffffu, mx1, 2));
        float mn0 = fmaxf(m0, mx0), mn1 = fmaxf(m1, mx1);
        float c0 = __expf(m0 - mn0), c1 = __expf(m1 - mn1);

        float s0 = 0.f, s1 = 0.f;
        #pragma unroll
        for (int nt = 0; nt < 8; nt++) {
            sc[nt][0] = __expf(sc[nt][0] - mn0);
            sc[nt][1] = __expf(sc[nt][1] - mn0);
            sc[nt][2] = __expf(sc[nt][2] - mn1);
            sc[nt][3] = __expf(sc[nt][3] - mn1);
            s0 += sc[nt][0] + sc[nt][1];
            s1 += sc[nt][2] + sc[nt][3];
        }
        s0 += __shfl_xor_sync(0xffffffffu, s0, 1);
        s0 += __shfl_xor_sync(0xffffffffu, s0, 2);
        s1 += __shfl_xor_sync(0xffffffffu, s1, 1);
        s1 += __shfl_xor_sync(0xffffffffu, s1, 2);
        l0 = l0 * c0 + s0;
        l1 = l1 * c1 + s1;
        m0 = mn0; m1 = mn1;
        #pragma unroll
        for (int nt = 0; nt < 16; nt++) {
            o[nt][0] *= c0; o[nt][1] *= c0;
            o[nt][2] *= c1; o[nt][3] *= c1;
        }

        #pragma unroll
        for (int j = 0; j < 4; j++) {
            unsigned pa[4];
            pa[0] = packh2(sc[2*j][0],   sc[2*j][1]);
            pa[1] = packh2(sc[2*j][2],   sc[2*j][3]);
            pa[2] = packh2(sc[2*j+1][0], sc[2*j+1][1]);
            pa[3] = packh2(sc[2*j+1][2], sc[2*j+1][3]);
            unsigned vrow = vbase + j * 16 * KVSTR * 2;
            #pragma unroll
            for (int p = 0; p < 8; p++) {
                unsigned vb[4];
                LDSM4T(vb, vrow + p * 32);
                mma16(o[2*p],   pa, vb[0], vb[1]);
                mma16(o[2*p+1], pa, vb[2], vb[3]);
            }
        }
        srd = (srd == 2) ? 0 : srd + 1;
        swr = (swr == 2) ? 0 : swr + 1;
    }

    float i0 = 1.f / l0, i1 = 1.f / l1;
    size_t r0 = (size_t)(b * SEQLEN + q0 + qrow0 + g) * DIM;
    size_t r1 = r0 + 8 * DIM;
    #pragma unroll
    for (int nt = 0; nt < 16; nt++) {
        int col = h * HD + nt * 8 + 2 * t;
        *(__half2*)&Oh[r0 + col] = __floats2half2_rn(o[nt][0] * i0, o[nt][1] * i0);
        *(__half2*)&Oh[r1 + col] = __floats2half2_rn(o[nt][2] * i1, o[nt][3] * i1);
    }
}

// ---------------- launch ----------------
extern "C" void kernel_launch(void* const* d_in, const int* in_sizes, int n_in,
                              void* d_out, int out_size) {
    const float* x     = (const float*)d_in[0];
    const int*   mask  = (const int*)  d_in[1];
    const float* fc    = (const float*)d_in[2];
    const float* fs    = (const float*)d_in[3];
    const float* qkv_w = (const float*)d_in[4];
    const float* out_w = (const float*)d_in[5];
    const float* s_q   = (const float*)d_in[6];
    const float* s_k   = (const float*)d_in[7];
    float* out = (float*)d_out;

    void *p0, *p1, *p2, *p3, *p4, *p5, *p6, *p7;
    cudaGetSymbolAddress(&p0, g_qkv);
    cudaGetSymbolAddress(&p1, g_xh);
    cudaGetSymbolAddress(&p2, g_wqh);
    cudaGetSymbolAddress(&p3, g_woh);
    cudaGetSymbolAddress(&p4, g_qh);
    cudaGetSymbolAddress(&p5, g_kh);
    cudaGetSymbolAddress(&p6, g_vh);
    cudaGetSymbolAddress(&p7, g_attnh);
    float*  qkv   = (float*)p0;
    __half* xh    = (__half*)p1;
    __half* wqh   = (__half*)p2;
    __half* woh   = (__half*)p3;
    __half* qh    = (__half*)p4;
    __half* kh    = (__half*)p5;
    __half* vh    = (__half*)p6;
    __half* attnh = (__half*)p7;

    cudaFuncSetAttribute(gemm_fp16, cudaFuncAttributeMaxDynamicSharedMemorySize, GEMM_SMEM);
    cudaFuncSetAttribute(flash_fp16, cudaFuncAttributeMaxDynamicSharedMemorySize, FSMEM);

    f2h_kernel<<<TOKENS * DIM / 8 / 256, 256>>>(x, xh, TOKENS * DIM);
    wnorm_half<<<QKV_OUT, 256>>>(qkv_w, wqh, DIM);
    wnorm_half<<<DIM, 256>>>(out_w, woh, DIM);

    gemm_fp16<<<dim3(QKV_OUT / 128, TOKENS / 128), 256, GEMM_SMEM>>>(
        xh, wqh, qkv, TOKENS, QKV_OUT, DIM);

    rope_half<<<TOKENS, 256>>>(qkv, fc, fs, s_q, s_k, qh, kh, vh);

    flash_fp16<<<dim3(SEQLEN / 128, NH, BSZ), 256, FSMEM>>>(qh, kh, vh, mask, attnh);

    gemm_fp16<<<dim3(DIM / 128, TOKENS / 128), 256, GEMM_SMEM>>>(
        attnh, woh, out, TOKENS, DIM, DIM);
}